// round 1
// baseline (speedup 1.0000x reference)
#include <cuda_runtime.h>
#include <math.h>

#define D_MODEL 1024
#define NHEAD   16
#define HEAD_DIM 64
#define BATCH   2
#define SEQ     2048
#define NTOK    (BATCH * SEQ)   // 4096

// ------------------------- scratch (no allocations allowed) -------------------------
__device__ float g_xn [NTOK * D_MODEL];
__device__ float g_q  [NTOK * D_MODEL];
__device__ float g_k  [NTOK * D_MODEL];
__device__ float g_v  [NTOK * D_MODEL];
__device__ float g_att[NTOK * D_MODEL];

// ------------------------------- LayerNorm ------------------------------------------
__global__ __launch_bounds__(256) void ln_kernel(const float* __restrict__ x,
                                                 const float* __restrict__ w,
                                                 const float* __restrict__ b,
                                                 float* __restrict__ y) {
    const int t   = blockIdx.x;
    const int tid = threadIdx.x;
    const float4* xr = reinterpret_cast<const float4*>(x + (size_t)t * D_MODEL);
    float4 v = xr[tid];

    __shared__ float red[8];
    float s = v.x + v.y + v.z + v.w;
    #pragma unroll
    for (int m = 16; m >= 1; m >>= 1) s += __shfl_xor_sync(0xffffffffu, s, m);
    if ((tid & 31) == 0) red[tid >> 5] = s;
    __syncthreads();
    float tot = 0.f;
    #pragma unroll
    for (int i = 0; i < 8; ++i) tot += red[i];
    const float mu = tot * (1.0f / D_MODEL);
    __syncthreads();

    const float dx = v.x - mu, dy = v.y - mu, dz = v.z - mu, dw = v.w - mu;
    float sq = dx*dx + dy*dy + dz*dz + dw*dw;
    #pragma unroll
    for (int m = 16; m >= 1; m >>= 1) sq += __shfl_xor_sync(0xffffffffu, sq, m);
    if ((tid & 31) == 0) red[tid >> 5] = sq;
    __syncthreads();
    float tot2 = 0.f;
    #pragma unroll
    for (int i = 0; i < 8; ++i) tot2 += red[i];
    const float var  = tot2 * (1.0f / D_MODEL);
    const float rstd = rsqrtf(var + 1e-5f);

    const float4 wv = reinterpret_cast<const float4*>(w)[tid];
    const float4 bv = reinterpret_cast<const float4*>(b)[tid];
    float4 o;
    o.x = dx * rstd * wv.x + bv.x;
    o.y = dy * rstd * wv.y + bv.y;
    o.z = dz * rstd * wv.z + bv.z;
    o.w = dw * rstd * wv.w + bv.w;
    reinterpret_cast<float4*>(y + (size_t)t * D_MODEL)[tid] = o;
}

// ------------------------------ SGEMM: C = A * W^T (+bias)(+resid) ------------------
// A: [M,K] row-major, W: [N,K] row-major (both K-major -> "NT" gemm).
#define GBM 128
#define GBN 128
#define GBK 16
#define GLDA (GBM + 4)

__global__ __launch_bounds__(256, 2) void gemm_nt(const float* __restrict__ A,
                                                  const float* __restrict__ W,
                                                  const float* __restrict__ bias,
                                                  const float* __restrict__ resid,
                                                  float* __restrict__ C,
                                                  int M, int N, int K) {
    __shared__ __align__(16) float As[2][GBK][GLDA];
    __shared__ __align__(16) float Ws[2][GBK][GLDA];

    const int tid = threadIdx.x;
    const int tx  = tid & 15;
    const int ty  = tid >> 4;
    const int m0  = blockIdx.y * GBM;
    const int n0  = blockIdx.x * GBN;
    const int lrow = tid >> 2;   // 0..63
    const int lc4  = tid & 3;    // 0..3 (float4 within 16-wide k slab)

    float acc[8][8];
    #pragma unroll
    for (int i = 0; i < 8; ++i)
        #pragma unroll
        for (int j = 0; j < 8; ++j) acc[i][j] = 0.f;

    const int nk = K / GBK;
    float4 a_reg[2], w_reg[2];

    // prefetch tile 0
    #pragma unroll
    for (int p = 0; p < 2; ++p) {
        a_reg[p] = *reinterpret_cast<const float4*>(A + (size_t)(m0 + lrow + 64*p) * K + lc4 * 4);
        w_reg[p] = *reinterpret_cast<const float4*>(W + (size_t)(n0 + lrow + 64*p) * K + lc4 * 4);
    }
    #pragma unroll
    for (int p = 0; p < 2; ++p) {
        const int r = lrow + 64*p;
        As[0][lc4*4+0][r] = a_reg[p].x;  As[0][lc4*4+1][r] = a_reg[p].y;
        As[0][lc4*4+2][r] = a_reg[p].z;  As[0][lc4*4+3][r] = a_reg[p].w;
        Ws[0][lc4*4+0][r] = w_reg[p].x;  Ws[0][lc4*4+1][r] = w_reg[p].y;
        Ws[0][lc4*4+2][r] = w_reg[p].z;  Ws[0][lc4*4+3][r] = w_reg[p].w;
    }
    __syncthreads();

    int buf = 0;
    for (int t = 0; t < nk; ++t) {
        if (t + 1 < nk) {
            const int k0 = (t + 1) * GBK;
            #pragma unroll
            for (int p = 0; p < 2; ++p) {
                a_reg[p] = *reinterpret_cast<const float4*>(A + (size_t)(m0 + lrow + 64*p) * K + k0 + lc4 * 4);
                w_reg[p] = *reinterpret_cast<const float4*>(W + (size_t)(n0 + lrow + 64*p) * K + k0 + lc4 * 4);
            }
        }
        #pragma unroll
        for (int kk = 0; kk < GBK; ++kk) {
            const float* Ar = &As[buf][kk][0];
            const float* Wr = &Ws[buf][kk][0];
            const float4 a0 = *reinterpret_cast<const float4*>(Ar + 4*ty);
            const float4 a1 = *reinterpret_cast<const float4*>(Ar + 64 + 4*ty);
            const float4 b0 = *reinterpret_cast<const float4*>(Wr + 4*tx);
            const float4 b1 = *reinterpret_cast<const float4*>(Wr + 64 + 4*tx);
            const float ar[8] = {a0.x,a0.y,a0.z,a0.w,a1.x,a1.y,a1.z,a1.w};
            const float br[8] = {b0.x,b0.y,b0.z,b0.w,b1.x,b1.y,b1.z,b1.w};
            #pragma unroll
            for (int i = 0; i < 8; ++i)
                #pragma unroll
                for (int j = 0; j < 8; ++j)
                    acc[i][j] += ar[i] * br[j];
        }
        if (t + 1 < nk) {
            const int nb = buf ^ 1;
            #pragma unroll
            for (int p = 0; p < 2; ++p) {
                const int r = lrow + 64*p;
                As[nb][lc4*4+0][r] = a_reg[p].x;  As[nb][lc4*4+1][r] = a_reg[p].y;
                As[nb][lc4*4+2][r] = a_reg[p].z;  As[nb][lc4*4+3][r] = a_reg[p].w;
                Ws[nb][lc4*4+0][r] = w_reg[p].x;  Ws[nb][lc4*4+1][r] = w_reg[p].y;
                Ws[nb][lc4*4+2][r] = w_reg[p].z;  Ws[nb][lc4*4+3][r] = w_reg[p].w;
            }
        }
        __syncthreads();
        buf ^= 1;
    }

    // epilogue
    #pragma unroll
    for (int ih = 0; ih < 2; ++ih) {
        #pragma unroll
        for (int i = 0; i < 4; ++i) {
            const int row = m0 + ih*64 + 4*ty + i;
            #pragma unroll
            for (int jh = 0; jh < 2; ++jh) {
                const int col = n0 + jh*64 + 4*tx;
                const float4 bz = *reinterpret_cast<const float4*>(bias + col);
                float4 r;
                r.x = acc[ih*4+i][jh*4+0] + bz.x;
                r.y = acc[ih*4+i][jh*4+1] + bz.y;
                r.z = acc[ih*4+i][jh*4+2] + bz.z;
                r.w = acc[ih*4+i][jh*4+3] + bz.w;
                if (resid) {
                    const float4 rv = *reinterpret_cast<const float4*>(resid + (size_t)row * N + col);
                    r.x += rv.x; r.y += rv.y; r.z += rv.z; r.w += rv.w;
                }
                *reinterpret_cast<float4*>(C + (size_t)row * N + col) = r;
            }
        }
    }
}

// --------------------------------- RoPE (in-place on q and k) -----------------------
__global__ __launch_bounds__(256) void rope_kernel(float* __restrict__ q, float* __restrict__ k) {
    const int idx = blockIdx.x * blockDim.x + threadIdx.x;   // < NTOK*512
    const int t   = idx >> 9;          // token
    const int rem = idx & 511;
    const int h   = rem >> 5;          // head
    const int j   = rem & 31;          // rotation pair
    const int n   = t & (SEQ - 1);     // position within sequence

    const float inv = expf(-(float)(2 * j) * (9.210340371976184f / 64.f)); // 10000^(-2j/64)
    const float ang = (float)n * inv;
    float sn, cs;
    sincosf(ang, &sn, &cs);

    const size_t base = (size_t)t * D_MODEL + h * HEAD_DIM + 2 * j;
    const float q0 = q[base], q1 = q[base + 1];
    q[base]     = q0 * cs - q1 * sn;
    q[base + 1] = q0 * sn + q1 * cs;
    const float k0 = k[base], k1 = k[base + 1];
    k[base]     = k0 * cs - k1 * sn;
    k[base + 1] = k0 * sn + k1 * cs;
}

// ------------------------------ flash attention (fp32) ------------------------------
// Block: (q-tile of 64, head, batch). 256 threads = 16x16, 4x4 micro-tiles.
#define APAD 68                       // 64 + 4 pad (keeps float4 alignment, kills conflicts)
#define ATT_SMEM (4 * 64 * APAD * 4)  // Qs, Ks, Vs, Ps

__global__ __launch_bounds__(256, 2) void attn_kernel(const float* __restrict__ qg,
                                                      const float* __restrict__ kg,
                                                      const float* __restrict__ vg,
                                                      float* __restrict__ og) {
    extern __shared__ float sm[];
    float* Qs = sm;
    float* Ks = sm + 64 * APAD;
    float* Vs = sm + 2 * 64 * APAD;
    float* Ps = sm + 3 * 64 * APAD;

    const int tid = threadIdx.x;
    const int tx  = tid & 15;
    const int ty  = tid >> 4;
    const int q0  = blockIdx.x * 64;
    const int h   = blockIdx.y;
    const int b   = blockIdx.z;
    const size_t cbase = (size_t)b * SEQ * D_MODEL + (size_t)h * HEAD_DIM;

    // load Q tile, pre-scaled by 1/sqrt(hd)
    for (int i = tid; i < 64 * 16; i += 256) {
        const int r = i >> 4, c4 = i & 15;
        float4 val = *reinterpret_cast<const float4*>(qg + cbase + (size_t)(q0 + r) * D_MODEL + c4 * 4);
        val.x *= 0.125f; val.y *= 0.125f; val.z *= 0.125f; val.w *= 0.125f;
        *reinterpret_cast<float4*>(&Qs[r * APAD + c4 * 4]) = val;
    }

    float oacc[4][4];
    float mrow[4], lrow[4];
    #pragma unroll
    for (int i = 0; i < 4; ++i) {
        mrow[i] = -1e30f; lrow[i] = 0.f;
        #pragma unroll
        for (int j = 0; j < 4; ++j) oacc[i][j] = 0.f;
    }

    for (int kt = 0; kt < SEQ / 64; ++kt) {
        // load K,V tile
        for (int i = tid; i < 64 * 16; i += 256) {
            const int r = i >> 4, c4 = i & 15;
            const size_t goff = cbase + (size_t)(kt * 64 + r) * D_MODEL + c4 * 4;
            *reinterpret_cast<float4*>(&Ks[r * APAD + c4 * 4]) = *reinterpret_cast<const float4*>(kg + goff);
            *reinterpret_cast<float4*>(&Vs[r * APAD + c4 * 4]) = *reinterpret_cast<const float4*>(vg + goff);
        }
        __syncthreads();

        // S = (Q*scale) K^T : thread owns rows 4ty..4ty+3, cols {tx+16j}
        float s[4][4];
        #pragma unroll
        for (int i = 0; i < 4; ++i)
            #pragma unroll
            for (int j = 0; j < 4; ++j) s[i][j] = 0.f;

        #pragma unroll
        for (int c = 0; c < 16; ++c) {
            float qv[4][4], kv[4][4];
            #pragma unroll
            for (int i = 0; i < 4; ++i) {
                const float4 tq = *reinterpret_cast<const float4*>(&Qs[(4*ty + i) * APAD + 4*c]);
                qv[i][0] = tq.x; qv[i][1] = tq.y; qv[i][2] = tq.z; qv[i][3] = tq.w;
            }
            #pragma unroll
            for (int j = 0; j < 4; ++j) {
                const float4 tk = *reinterpret_cast<const float4*>(&Ks[(tx + 16*j) * APAD + 4*c]);
                kv[j][0] = tk.x; kv[j][1] = tk.y; kv[j][2] = tk.z; kv[j][3] = tk.w;
            }
            #pragma unroll
            for (int i = 0; i < 4; ++i)
                #pragma unroll
                for (int j = 0; j < 4; ++j)
                    #pragma unroll
                    for (int d = 0; d < 4; ++d)
                        s[i][j] += qv[i][d] * kv[j][d];
        }

        // online softmax (row reduction across the 16 threads of a thread-row)
        #pragma unroll
        for (int i = 0; i < 4; ++i) {
            float rm = fmaxf(fmaxf(s[i][0], s[i][1]), fmaxf(s[i][2], s[i][3]));
            #pragma unroll
            for (int m = 8; m >= 1; m >>= 1) rm = fmaxf(rm, __shfl_xor_sync(0xffffffffu, rm, m));
            const float mnew = fmaxf(mrow[i], rm);
            const float corr = __expf(mrow[i] - mnew);
            float ps = 0.f;
            #pragma unroll
            for (int j = 0; j < 4; ++j) {
                const float p = __expf(s[i][j] - mnew);
                Ps[(4*ty + i) * APAD + tx + 16*j] = p;
                ps += p;
            }
            #pragma unroll
            for (int m = 8; m >= 1; m >>= 1) ps += __shfl_xor_sync(0xffffffffu, ps, m);
            lrow[i] = lrow[i] * corr + ps;
            mrow[i] = mnew;
            #pragma unroll
            for (int j = 0; j < 4; ++j) oacc[i][j] *= corr;
        }
        __syncthreads();

        // O += P V : thread owns O rows 4ty..4ty+3, cols 4tx..4tx+3
        #pragma unroll
        for (int c = 0; c < 16; ++c) {
            float pv[4][4], vv[4][4];
            #pragma unroll
            for (int i = 0; i < 4; ++i) {
                const float4 tp = *reinterpret_cast<const float4*>(&Ps[(4*ty + i) * APAD + 4*c]);
                pv[i][0] = tp.x; pv[i][1] = tp.y; pv[i][2] = tp.z; pv[i][3] = tp.w;
            }
            #pragma unroll
            for (int t2 = 0; t2 < 4; ++t2) {
                const float4 tv = *reinterpret_cast<const float4*>(&Vs[(4*c + t2) * APAD + 4*tx]);
                vv[t2][0] = tv.x; vv[t2][1] = tv.y; vv[t2][2] = tv.z; vv[t2][3] = tv.w;
            }
            #pragma unroll
            for (int i = 0; i < 4; ++i)
                #pragma unroll
                for (int t2 = 0; t2 < 4; ++t2)
                    #pragma unroll
                    for (int j = 0; j < 4; ++j)
                        oacc[i][j] += pv[i][t2] * vv[t2][j];
        }
        __syncthreads();
    }

    #pragma unroll
    for (int i = 0; i < 4; ++i) {
        const float inv = 1.f / lrow[i];
        float4 outv;
        outv.x = oacc[i][0] * inv; outv.y = oacc[i][1] * inv;
        outv.z = oacc[i][2] * inv; outv.w = oacc[i][3] * inv;
        *reinterpret_cast<float4*>(og + cbase + (size_t)(q0 + 4*ty + i) * D_MODEL + 4*tx) = outv;
    }
}

// ---------------------------------- launch ------------------------------------------
extern "C" void kernel_launch(void* const* d_in, const int* in_sizes, int n_in,
                              void* d_out, int out_size) {
    const float* x    = (const float*)d_in[0];
    const float* ln_w = (const float*)d_in[1];
    const float* ln_b = (const float*)d_in[2];
    const float* Wq   = (const float*)d_in[3];
    const float* bq   = (const float*)d_in[4];
    const float* Wk   = (const float*)d_in[5];
    const float* bk   = (const float*)d_in[6];
    const float* Wv   = (const float*)d_in[7];
    const float* bv   = (const float*)d_in[8];
    const float* Wo   = (const float*)d_in[9];
    const float* bo   = (const float*)d_in[10];
    float* out = (float*)d_out;

    float *xn, *q, *k, *v, *att;
    cudaGetSymbolAddress((void**)&xn,  g_xn);
    cudaGetSymbolAddress((void**)&q,   g_q);
    cudaGetSymbolAddress((void**)&k,   g_k);
    cudaGetSymbolAddress((void**)&v,   g_v);
    cudaGetSymbolAddress((void**)&att, g_att);

    ln_kernel<<<NTOK, 256>>>(x, ln_w, ln_b, xn);

    dim3 ggrid(D_MODEL / GBN, NTOK / GBM);   // (8, 32)
    gemm_nt<<<ggrid, 256>>>(xn, Wq, bq, nullptr, q, NTOK, D_MODEL, D_MODEL);
    gemm_nt<<<ggrid, 256>>>(xn, Wk, bk, nullptr, k, NTOK, D_MODEL, D_MODEL);
    gemm_nt<<<ggrid, 256>>>(xn, Wv, bv, nullptr, v, NTOK, D_MODEL, D_MODEL);

    rope_kernel<<<(NTOK * 512) / 256, 256>>>(q, k);

    cudaFuncSetAttribute(attn_kernel, cudaFuncAttributeMaxDynamicSharedMemorySize, ATT_SMEM);
    attn_kernel<<<dim3(SEQ / 64, NHEAD, BATCH), 256, ATT_SMEM>>>(q, k, v, att);

    gemm_nt<<<ggrid, 256>>>(att, Wo, bo, x, out, NTOK, D_MODEL, D_MODEL);
}

// round 2
// speedup vs baseline: 2.3706x; 2.3706x over previous
#include <cuda_runtime.h>
#include <math.h>
#include <stdint.h>

#define D_MODEL 1024
#define NHEAD   16
#define HEAD_DIM 64
#define BATCH   2
#define SEQ     2048
#define NTOK    (BATCH * SEQ)   // 4096

// ------------------------- scratch (no allocations allowed) -------------------------
__device__ float g_xn [NTOK * D_MODEL];
__device__ float g_q  [NTOK * D_MODEL];
__device__ float g_k  [NTOK * D_MODEL];
__device__ float g_v  [NTOK * D_MODEL];
__device__ float g_att[NTOK * D_MODEL];

// ------------------------------- helpers --------------------------------------------
__device__ __forceinline__ uint32_t cvt_tf32(float x) {
    uint32_t r;
    asm("cvt.rna.tf32.f32 %0, %1;" : "=r"(r) : "f"(x));
    return r;
}

__device__ __forceinline__ void mma_tf32(float* d, const uint32_t* a, const uint32_t* b) {
    asm volatile(
        "mma.sync.aligned.m16n8k8.row.col.f32.tf32.tf32.f32 "
        "{%0,%1,%2,%3}, {%4,%5,%6,%7}, {%8,%9}, {%0,%1,%2,%3};"
        : "+f"(d[0]), "+f"(d[1]), "+f"(d[2]), "+f"(d[3])
        : "r"(a[0]), "r"(a[1]), "r"(a[2]), "r"(a[3]), "r"(b[0]), "r"(b[1]));
}

__device__ __forceinline__ uint32_t smem_u32(const void* p) {
    return (uint32_t)__cvta_generic_to_shared(p);
}
__device__ __forceinline__ void cp16(uint32_t s, const void* g) {
    asm volatile("cp.async.cg.shared.global [%0], [%1], 16;" :: "r"(s), "l"(g));
}
#define CP_COMMIT   asm volatile("cp.async.commit_group;")
#define CP_WAIT_ALL asm volatile("cp.async.wait_all;")

// ------------------------------- LayerNorm ------------------------------------------
__global__ __launch_bounds__(256) void ln_kernel(const float* __restrict__ x,
                                                 const float* __restrict__ w,
                                                 const float* __restrict__ b,
                                                 float* __restrict__ y) {
    const int t   = blockIdx.x;
    const int tid = threadIdx.x;
    const float4* xr = reinterpret_cast<const float4*>(x + (size_t)t * D_MODEL);
    float4 v = xr[tid];

    __shared__ float red[8];
    float s = v.x + v.y + v.z + v.w;
    #pragma unroll
    for (int m = 16; m >= 1; m >>= 1) s += __shfl_xor_sync(0xffffffffu, s, m);
    if ((tid & 31) == 0) red[tid >> 5] = s;
    __syncthreads();
    float tot = 0.f;
    #pragma unroll
    for (int i = 0; i < 8; ++i) tot += red[i];
    const float mu = tot * (1.0f / D_MODEL);
    __syncthreads();

    const float dx = v.x - mu, dy = v.y - mu, dz = v.z - mu, dw = v.w - mu;
    float sq = dx*dx + dy*dy + dz*dz + dw*dw;
    #pragma unroll
    for (int m = 16; m >= 1; m >>= 1) sq += __shfl_xor_sync(0xffffffffu, sq, m);
    if ((tid & 31) == 0) red[tid >> 5] = sq;
    __syncthreads();
    float tot2 = 0.f;
    #pragma unroll
    for (int i = 0; i < 8; ++i) tot2 += red[i];
    const float rstd = rsqrtf(tot2 * (1.0f / D_MODEL) + 1e-5f);

    const float4 wv = reinterpret_cast<const float4*>(w)[tid];
    const float4 bv = reinterpret_cast<const float4*>(b)[tid];
    float4 o;
    o.x = dx * rstd * wv.x + bv.x;
    o.y = dy * rstd * wv.y + bv.y;
    o.z = dz * rstd * wv.z + bv.z;
    o.w = dw * rstd * wv.w + bv.w;
    reinterpret_cast<float4*>(y + (size_t)t * D_MODEL)[tid] = o;
}

// ------------------------- TF32 tensor-core GEMM: C = A * W^T (+bias)(+resid) -------
// A: [M,K] row-major, W: [N,K] row-major. 128x128x32 tiles, cp.async double buffer.
#define TBM 128
#define TBN 128
#define TBK 32
#define GLD 36   // 32 + 4 float pad: frag LDS bank = 4g+t (conflict-free)
#define GEMM_SMEM (4 * 4608 * 4)   // 2 bufs x (A 128*36 + W 128*36) floats

__global__ __launch_bounds__(256, 2) void gemm_tc(const float* __restrict__ A,
                                                  const float* __restrict__ W,
                                                  const float* __restrict__ bias,
                                                  const float* __restrict__ resid,
                                                  float* __restrict__ C,
                                                  int M, int N, int K) {
    extern __shared__ float sm[];
    float* Ab[2] = { sm,        sm + 4608  };
    float* Wb[2] = { sm + 9216, sm + 13824 };

    const int tid  = threadIdx.x;
    const int m0   = blockIdx.y * TBM;
    const int n0   = blockIdx.x * TBN;
    const int wid  = tid >> 5, lane = tid & 31;
    const int wm   = wid >> 2, wn   = wid & 3;     // 2 x 4 warps
    const int g    = lane >> 2, t   = lane & 3;

    // loader mapping: 1024 16B chunks per matrix, 4 per thread
    const int lr  = tid >> 1;              // unused pattern replaced below
    (void)lr;

    float acc[4][4][4];
    #pragma unroll
    for (int a = 0; a < 4; ++a)
        #pragma unroll
        for (int b = 0; b < 4; ++b)
            #pragma unroll
            for (int c = 0; c < 4; ++c) acc[a][b][c] = 0.f;

    const int nk = K / TBK;

    // prologue: tile 0
    #pragma unroll
    for (int c = 0; c < 4; ++c) {
        const int j  = tid + (c << 8);
        const int r  = j >> 3, k4 = (j & 7) << 2;
        cp16(smem_u32(&Ab[0][r * GLD + k4]), A + (size_t)(m0 + r) * K + k4);
        cp16(smem_u32(&Wb[0][r * GLD + k4]), W + (size_t)(n0 + r) * K + k4);
    }
    CP_COMMIT;

    int cur = 0;
    for (int tt = 0; tt < nk; ++tt) {
        CP_WAIT_ALL;
        __syncthreads();
        if (tt + 1 < nk) {
            const int kp = (tt + 1) * TBK;
            #pragma unroll
            for (int c = 0; c < 4; ++c) {
                const int j  = tid + (c << 8);
                const int r  = j >> 3, k4 = (j & 7) << 2;
                cp16(smem_u32(&Ab[cur ^ 1][r * GLD + k4]), A + (size_t)(m0 + r) * K + kp + k4);
                cp16(smem_u32(&Wb[cur ^ 1][r * GLD + k4]), W + (size_t)(n0 + r) * K + kp + k4);
            }
            CP_COMMIT;
        }
        #pragma unroll
        for (int s8 = 0; s8 < 4; ++s8) {
            const int k0 = s8 * 8;
            uint32_t af[4][4], bf[4][2];
            #pragma unroll
            for (int mf = 0; mf < 4; ++mf) {
                const float* ab = &Ab[cur][(wm * 64 + mf * 16 + g) * GLD + k0 + t];
                af[mf][0] = cvt_tf32(ab[0]);
                af[mf][1] = cvt_tf32(ab[8 * GLD]);
                af[mf][2] = cvt_tf32(ab[4]);
                af[mf][3] = cvt_tf32(ab[8 * GLD + 4]);
            }
            #pragma unroll
            for (int nf = 0; nf < 4; ++nf) {
                const float* wb = &Wb[cur][(wn * 32 + nf * 8 + g) * GLD + k0 + t];
                bf[nf][0] = cvt_tf32(wb[0]);
                bf[nf][1] = cvt_tf32(wb[4]);
            }
            #pragma unroll
            for (int mf = 0; mf < 4; ++mf)
                #pragma unroll
                for (int nf = 0; nf < 4; ++nf)
                    mma_tf32(acc[mf][nf], af[mf], bf[nf]);
        }
        cur ^= 1;
    }

    // epilogue: C layout c0=C[g][2t], c1=C[g][2t+1], c2=C[g+8][2t], c3=C[g+8][2t+1]
    #pragma unroll
    for (int mf = 0; mf < 4; ++mf) {
        #pragma unroll
        for (int nf = 0; nf < 4; ++nf) {
            const int n = n0 + wn * 32 + nf * 8 + 2 * t;
            const float2 bz = *(const float2*)(bias + n);
            #pragma unroll
            for (int h = 0; h < 2; ++h) {
                const int m = m0 + wm * 64 + mf * 16 + g + 8 * h;
                float2 r2;
                r2.x = acc[mf][nf][2 * h + 0] + bz.x;
                r2.y = acc[mf][nf][2 * h + 1] + bz.y;
                if (resid) {
                    const float2 rv = *(const float2*)(resid + (size_t)m * N + n);
                    r2.x += rv.x; r2.y += rv.y;
                }
                *(float2*)(C + (size_t)m * N + n) = r2;
            }
        }
    }
}

// --------------------------------- RoPE (in-place on q and k) -----------------------
__global__ __launch_bounds__(256) void rope_kernel(float* __restrict__ q, float* __restrict__ k) {
    const int idx = blockIdx.x * blockDim.x + threadIdx.x;
    const int t   = idx >> 9;
    const int rem = idx & 511;
    const int h   = rem >> 5;
    const int j   = rem & 31;
    const int n   = t & (SEQ - 1);

    const float inv = expf(-(float)(2 * j) * (9.210340371976184f / 64.f));
    float sn, cs;
    sincosf((float)n * inv, &sn, &cs);

    const size_t base = (size_t)t * D_MODEL + h * HEAD_DIM + 2 * j;
    const float q0 = q[base], q1 = q[base + 1];
    q[base]     = q0 * cs - q1 * sn;
    q[base + 1] = q0 * sn + q1 * cs;
    const float k0 = k[base], k1 = k[base + 1];
    k[base]     = k0 * cs - k1 * sn;
    k[base + 1] = k0 * sn + k1 * cs;
}

// ------------------------ flash attention, TF32 tensor cores ------------------------
// q-tile 128, k-tile 64, hd 64. 256 threads = 8 warps, each warp owns 16 q rows.
#define AQ  128
#define AKT 64
#define ALD 68   // 64 + 4 pad
#define NT  (SEQ / AKT)  // 32
// smem floats: Qs 128*68 + Ks 64*68 + Vst(uint) 64*68 + Ps(uint) 128*68
#define ATT_SMEM ((128*ALD + 64*ALD + 64*ALD + 128*ALD) * 4)

__global__ __launch_bounds__(256, 2) void attn_tc(const float* __restrict__ qg,
                                                  const float* __restrict__ kg,
                                                  const float* __restrict__ vg,
                                                  float* __restrict__ og) {
    extern __shared__ float sm[];
    float*    Qs  = sm;                                   // [128][68] raw f32
    float*    Ks  = Qs + 128 * ALD;                       // [64][68]  raw f32 (rows=key)
    uint32_t* Vst = (uint32_t*)(Ks + 64 * ALD);           // [64(d)][68(key)] tf32, transposed
    uint32_t* Ps  = (uint32_t*)(Vst + 64 * ALD);          // [128(q)][68(key)] tf32

    const int tid  = threadIdx.x, wid = tid >> 5, lane = tid & 31;
    const int g    = lane >> 2, t = lane & 3;
    const int q0   = blockIdx.x * AQ;
    const size_t cbase = (size_t)blockIdx.z * SEQ * D_MODEL + (size_t)blockIdx.y * HEAD_DIM;
    const int wrow = wid * 16;

    // ---- prologue loads ----
    // Q: 128 rows x 16 chunks = 2048 chunks, 8/thread (cp.async, raw f32)
    #pragma unroll
    for (int c = 0; c < 8; ++c) {
        const int j = tid + (c << 8);
        const int r = j >> 4, k4 = (j & 15) << 2;
        cp16(smem_u32(&Qs[r * ALD + k4]), qg + cbase + (size_t)(q0 + r) * D_MODEL + k4);
    }
    // K tile 0 via cp.async (natural [key][d] layout)
    #pragma unroll
    for (int c = 0; c < 4; ++c) {
        const int j = tid + (c << 8);
        const int r = j >> 4, k4 = (j & 15) << 2;
        cp16(smem_u32(&Ks[r * ALD + k4]), kg + cbase + (size_t)r * D_MODEL + k4);
    }
    CP_COMMIT;
    // V tile 0: manual transposed store, cvt to tf32: Vst[d][key]
    #pragma unroll
    for (int c = 0; c < 4; ++c) {
        const int j = tid + (c << 8);
        const int r = j >> 4, k4 = (j & 15) << 2;   // key row r, dims k4..k4+3
        const float4 v4 = *(const float4*)(vg + cbase + (size_t)r * D_MODEL + k4);
        Vst[(k4 + 0) * ALD + r] = cvt_tf32(v4.x);
        Vst[(k4 + 1) * ALD + r] = cvt_tf32(v4.y);
        Vst[(k4 + 2) * ALD + r] = cvt_tf32(v4.z);
        Vst[(k4 + 3) * ALD + r] = cvt_tf32(v4.w);
    }
    CP_WAIT_ALL;
    __syncthreads();

    float oacc[8][4];
    float mst[2] = { -1e30f, -1e30f }, lst[2] = { 0.f, 0.f };
    #pragma unroll
    for (int df = 0; df < 8; ++df)
        #pragma unroll
        for (int c = 0; c < 4; ++c) oacc[df][c] = 0.f;

    for (int kt = 0; kt < NT; ++kt) {
        // ---- S = Q K^T (warp rows wrow..wrow+15, all 64 key cols) ----
        float sacc[8][4];
        #pragma unroll
        for (int nf = 0; nf < 8; ++nf)
            #pragma unroll
            for (int c = 0; c < 4; ++c) sacc[nf][c] = 0.f;

        #pragma unroll
        for (int s8 = 0; s8 < 8; ++s8) {
            const int k0 = s8 * 8;
            uint32_t af[4];
            const float* qb = &Qs[(wrow + g) * ALD + k0 + t];
            af[0] = cvt_tf32(qb[0]);
            af[1] = cvt_tf32(qb[8 * ALD]);
            af[2] = cvt_tf32(qb[4]);
            af[3] = cvt_tf32(qb[8 * ALD + 4]);
            #pragma unroll
            for (int nf = 0; nf < 8; ++nf) {
                uint32_t bf[2];
                const float* kb = &Ks[(nf * 8 + g) * ALD + k0 + t];
                bf[0] = cvt_tf32(kb[0]);
                bf[1] = cvt_tf32(kb[4]);
                mma_tf32(sacc[nf], af, bf);
            }
        }

        // ---- online softmax (rows g and g+8, warp-local over 4 lanes) ----
        #pragma unroll
        for (int h = 0; h < 2; ++h) {
            float rm = -1e30f;
            #pragma unroll
            for (int nf = 0; nf < 8; ++nf)
                rm = fmaxf(rm, fmaxf(sacc[nf][2 * h], sacc[nf][2 * h + 1]));
            rm *= 0.125f;
            rm = fmaxf(rm, __shfl_xor_sync(0xffffffffu, rm, 1));
            rm = fmaxf(rm, __shfl_xor_sync(0xffffffffu, rm, 2));
            const float mnew = fmaxf(mst[h], rm);
            const float corr = __expf(mst[h] - mnew);
            float ps = 0.f;
            const int prow = wrow + g + 8 * h;
            #pragma unroll
            for (int nf = 0; nf < 8; ++nf) {
                const float p0 = __expf(sacc[nf][2 * h] * 0.125f - mnew);
                const float p1 = __expf(sacc[nf][2 * h + 1] * 0.125f - mnew);
                ps += p0 + p1;
                uint2 pu; pu.x = cvt_tf32(p0); pu.y = cvt_tf32(p1);
                *(uint2*)&Ps[prow * ALD + nf * 8 + 2 * t] = pu;
            }
            ps += __shfl_xor_sync(0xffffffffu, ps, 1);
            ps += __shfl_xor_sync(0xffffffffu, ps, 2);
            lst[h] = lst[h] * corr + ps;
            mst[h] = mnew;
            #pragma unroll
            for (int df = 0; df < 8; ++df) {
                oacc[df][2 * h]     *= corr;
                oacc[df][2 * h + 1] *= corr;
            }
        }
        __syncwarp();

        __syncthreads();   // all warps done reading Ks
        if (kt + 1 < NT) { // overlap K(kt+1) copy with PV compute
            #pragma unroll
            for (int c = 0; c < 4; ++c) {
                const int j = tid + (c << 8);
                const int r = j >> 4, k4 = (j & 15) << 2;
                cp16(smem_u32(&Ks[r * ALD + k4]),
                     kg + cbase + (size_t)((kt + 1) * AKT + r) * D_MODEL + k4);
            }
            CP_COMMIT;
        }

        // ---- O += P V ----
        #pragma unroll
        for (int s8 = 0; s8 < 8; ++s8) {
            const int k0 = s8 * 8;
            uint32_t af[4];
            const uint32_t* pb = &Ps[(wrow + g) * ALD + k0 + t];
            af[0] = pb[0];
            af[1] = pb[8 * ALD];
            af[2] = pb[4];
            af[3] = pb[8 * ALD + 4];
            #pragma unroll
            for (int df = 0; df < 8; ++df) {
                uint32_t bf[2];
                const uint32_t* vb = &Vst[0];
                bf[0] = Vst[(df * 8 + g) * ALD + k0 + t];
                bf[1] = Vst[(df * 8 + g) * ALD + k0 + t + 4];
                (void)vb;
                mma_tf32(oacc[df], af, bf);
            }
        }

        __syncthreads();   // all warps done reading Vst
        if (kt + 1 < NT) {
            #pragma unroll
            for (int c = 0; c < 4; ++c) {
                const int j = tid + (c << 8);
                const int r = j >> 4, k4 = (j & 15) << 2;
                const float4 v4 = *(const float4*)(vg + cbase +
                                   (size_t)((kt + 1) * AKT + r) * D_MODEL + k4);
                Vst[(k4 + 0) * ALD + r] = cvt_tf32(v4.x);
                Vst[(k4 + 1) * ALD + r] = cvt_tf32(v4.y);
                Vst[(k4 + 2) * ALD + r] = cvt_tf32(v4.z);
                Vst[(k4 + 3) * ALD + r] = cvt_tf32(v4.w);
            }
            CP_WAIT_ALL;
        }
        __syncthreads();   // K(kt+1)/V(kt+1) visible for next iter
    }

    // ---- finalize: divide by l, write out ----
    #pragma unroll
    for (int h = 0; h < 2; ++h) {
        const float inv = 1.f / lst[h];
        const int row = q0 + wrow + g + 8 * h;
        #pragma unroll
        for (int df = 0; df < 8; ++df) {
            float2 o2;
            o2.x = oacc[df][2 * h]     * inv;
            o2.y = oacc[df][2 * h + 1] * inv;
            *(float2*)(og + cbase + (size_t)row * D_MODEL + df * 8 + 2 * t) = o2;
        }
    }
}

// NOTE on PV fragment layout: A = P (rows=q, k=key) from Ps[q][key];
// B = V with B[k=key][n=d] = V[key][d], stored transposed as Vst[d][key] so the
// b-frag read Vst[(8*df+g)*ALD + k0+t] is conflict-free (bank = 4g+t).

// ---------------------------------- launch ------------------------------------------
extern "C" void kernel_launch(void* const* d_in, const int* in_sizes, int n_in,
                              void* d_out, int out_size) {
    const float* x    = (const float*)d_in[0];
    const float* ln_w = (const float*)d_in[1];
    const float* ln_b = (const float*)d_in[2];
    const float* Wq   = (const float*)d_in[3];
    const float* bq   = (const float*)d_in[4];
    const float* Wk   = (const float*)d_in[5];
    const float* bk   = (const float*)d_in[6];
    const float* Wv   = (const float*)d_in[7];
    const float* bv   = (const float*)d_in[8];
    const float* Wo   = (const float*)d_in[9];
    const float* bo   = (const float*)d_in[10];
    float* out = (float*)d_out;

    float *xn, *q, *k, *v, *att;
    cudaGetSymbolAddress((void**)&xn,  g_xn);
    cudaGetSymbolAddress((void**)&q,   g_q);
    cudaGetSymbolAddress((void**)&k,   g_k);
    cudaGetSymbolAddress((void**)&v,   g_v);
    cudaGetSymbolAddress((void**)&att, g_att);

    ln_kernel<<<NTOK, 256>>>(x, ln_w, ln_b, xn);

    cudaFuncSetAttribute(gemm_tc, cudaFuncAttributeMaxDynamicSharedMemorySize, GEMM_SMEM);
    dim3 ggrid(D_MODEL / TBN, NTOK / TBM);   // (8, 32)
    gemm_tc<<<ggrid, 256, GEMM_SMEM>>>(xn, Wq, bq, nullptr, q, NTOK, D_MODEL, D_MODEL);
    gemm_tc<<<ggrid, 256, GEMM_SMEM>>>(xn, Wk, bk, nullptr, k, NTOK, D_MODEL, D_MODEL);
    gemm_tc<<<ggrid, 256, GEMM_SMEM>>>(xn, Wv, bv, nullptr, v, NTOK, D_MODEL, D_MODEL);

    rope_kernel<<<(NTOK * 512) / 256, 256>>>(q, k);

    cudaFuncSetAttribute(attn_tc, cudaFuncAttributeMaxDynamicSharedMemorySize, ATT_SMEM);
    attn_tc<<<dim3(SEQ / AQ, NHEAD, BATCH), 256, ATT_SMEM>>>(q, k, v, att);

    gemm_tc<<<ggrid, 256, GEMM_SMEM>>>(att, Wo, bo, x, out, NTOK, D_MODEL, D_MODEL);
}

// round 4
// speedup vs baseline: 2.6043x; 1.0986x over previous
#include <cuda_runtime.h>
#include <math.h>
#include <stdint.h>

#define D_MODEL 1024
#define NHEAD   16
#define HEAD_DIM 64
#define BATCH   2
#define SEQ     2048
#define NTOK    (BATCH * SEQ)   // 4096

// ------------------------- scratch (no allocations allowed) -------------------------
__device__ float g_xn [NTOK * D_MODEL];
__device__ float g_q  [NTOK * D_MODEL];
__device__ float g_k  [NTOK * D_MODEL];
__device__ float g_v  [NTOK * D_MODEL];
__device__ float g_att[NTOK * D_MODEL];
__device__ float g_w  [4 * D_MODEL * D_MODEL];   // tf32-rounded Wq,Wk,Wv,Wo

// ------------------------------- helpers --------------------------------------------
__device__ __forceinline__ uint32_t cvt_tf32(float x) {
    uint32_t r;
    asm("cvt.rna.tf32.f32 %0, %1;" : "=r"(r) : "f"(x));
    return r;
}
__device__ __forceinline__ float round_tf32(float x) {
    return __uint_as_float(cvt_tf32(x));
}
__device__ __forceinline__ void mma_tf32(float* d, const uint32_t* a, const uint32_t* b) {
    asm volatile(
        "mma.sync.aligned.m16n8k8.row.col.f32.tf32.tf32.f32 "
        "{%0,%1,%2,%3}, {%4,%5,%6,%7}, {%8,%9}, {%0,%1,%2,%3};"
        : "+f"(d[0]), "+f"(d[1]), "+f"(d[2]), "+f"(d[3])
        : "r"(a[0]), "r"(a[1]), "r"(a[2]), "r"(a[3]), "r"(b[0]), "r"(b[1]));
}
__device__ __forceinline__ uint32_t smem_u32(const void* p) {
    return (uint32_t)__cvta_generic_to_shared(p);
}
__device__ __forceinline__ void cp16(uint32_t s, const void* g) {
    asm volatile("cp.async.cg.shared.global [%0], [%1], 16;" :: "r"(s), "l"(g));
}
#define CP_COMMIT   asm volatile("cp.async.commit_group;")
#define CP_WAIT_ALL asm volatile("cp.async.wait_all;")

// ------------------------------- weight pre-round -----------------------------------
__global__ __launch_bounds__(256) void round_w_kernel(const float* __restrict__ a,
                                                      const float* __restrict__ b,
                                                      const float* __restrict__ c,
                                                      const float* __restrict__ d,
                                                      float* __restrict__ o) {
    const int i = blockIdx.x * 256 + threadIdx.x;          // float4 index
    const int n4 = D_MODEL * D_MODEL / 4;
    const float4 va = reinterpret_cast<const float4*>(a)[i];
    const float4 vb = reinterpret_cast<const float4*>(b)[i];
    const float4 vc = reinterpret_cast<const float4*>(c)[i];
    const float4 vd = reinterpret_cast<const float4*>(d)[i];
    float4 r;
    r.x = round_tf32(va.x); r.y = round_tf32(va.y); r.z = round_tf32(va.z); r.w = round_tf32(va.w);
    reinterpret_cast<float4*>(o)[i] = r;
    r.x = round_tf32(vb.x); r.y = round_tf32(vb.y); r.z = round_tf32(vb.z); r.w = round_tf32(vb.w);
    reinterpret_cast<float4*>(o)[n4 + i] = r;
    r.x = round_tf32(vc.x); r.y = round_tf32(vc.y); r.z = round_tf32(vc.z); r.w = round_tf32(vc.w);
    reinterpret_cast<float4*>(o)[2 * n4 + i] = r;
    r.x = round_tf32(vd.x); r.y = round_tf32(vd.y); r.z = round_tf32(vd.z); r.w = round_tf32(vd.w);
    reinterpret_cast<float4*>(o)[3 * n4 + i] = r;
}

// ------------------------------- LayerNorm (tf32-rounded out) -----------------------
__global__ __launch_bounds__(256) void ln_kernel(const float* __restrict__ x,
                                                 const float* __restrict__ w,
                                                 const float* __restrict__ b,
                                                 float* __restrict__ y) {
    const int t   = blockIdx.x;
    const int tid = threadIdx.x;
    const float4* xr = reinterpret_cast<const float4*>(x + (size_t)t * D_MODEL);
    float4 v = xr[tid];

    __shared__ float red[8];
    float s = v.x + v.y + v.z + v.w;
    #pragma unroll
    for (int m = 16; m >= 1; m >>= 1) s += __shfl_xor_sync(0xffffffffu, s, m);
    if ((tid & 31) == 0) red[tid >> 5] = s;
    __syncthreads();
    float tot = 0.f;
    #pragma unroll
    for (int i = 0; i < 8; ++i) tot += red[i];
    const float mu = tot * (1.0f / D_MODEL);
    __syncthreads();

    const float dx = v.x - mu, dy = v.y - mu, dz = v.z - mu, dw = v.w - mu;
    float sq = dx*dx + dy*dy + dz*dz + dw*dw;
    #pragma unroll
    for (int m = 16; m >= 1; m >>= 1) sq += __shfl_xor_sync(0xffffffffu, sq, m);
    if ((tid & 31) == 0) red[tid >> 5] = sq;
    __syncthreads();
    float tot2 = 0.f;
    #pragma unroll
    for (int i = 0; i < 8; ++i) tot2 += red[i];
    const float rstd = rsqrtf(tot2 * (1.0f / D_MODEL) + 1e-5f);

    const float4 wv = reinterpret_cast<const float4*>(w)[tid];
    const float4 bv = reinterpret_cast<const float4*>(b)[tid];
    float4 o;
    o.x = round_tf32(dx * rstd * wv.x + bv.x);
    o.y = round_tf32(dy * rstd * wv.y + bv.y);
    o.z = round_tf32(dz * rstd * wv.z + bv.z);
    o.w = round_tf32(dw * rstd * wv.w + bv.w);
    reinterpret_cast<float4*>(y + (size_t)t * D_MODEL)[tid] = o;
}

// ------------------------- TF32 tensor-core GEMM core -------------------------------
// A: [M,K] row-major (tf32-valued), W: [N,K] row-major (tf32-valued).
// 128x128x32 tiles, cp.async double buffer, NO cvt in the hot loop.
#define TBM 128
#define TBN 128
#define TBK 32
#define GLD 36   // 32 + 4 float pad
#define GEMM_SMEM (4 * 4608 * 4)

struct GemmOut {
    float* C;
    const float* bias;
    const float* resid;
    int round_out;
};

__device__ __forceinline__ void gemm_body(const float* __restrict__ A,
                                          const float* __restrict__ W,
                                          const GemmOut& out,
                                          int m0, int n0, float* sm) {
    float* Ab[2] = { sm,        sm + 4608  };
    float* Wb[2] = { sm + 9216, sm + 13824 };

    const int tid  = threadIdx.x;
    const int wid  = tid >> 5, lane = tid & 31;
    const int wm   = wid >> 2, wn   = wid & 3;     // 2 x 4 warps
    const int g    = lane >> 2, t   = lane & 3;

    float acc[4][4][4];
    #pragma unroll
    for (int a = 0; a < 4; ++a)
        #pragma unroll
        for (int b = 0; b < 4; ++b)
            #pragma unroll
            for (int c = 0; c < 4; ++c) acc[a][b][c] = 0.f;

    const int nk = D_MODEL / TBK;

    #pragma unroll
    for (int c = 0; c < 4; ++c) {
        const int j  = tid + (c << 8);
        const int r  = j >> 3, k4 = (j & 7) << 2;
        cp16(smem_u32(&Ab[0][r * GLD + k4]), A + (size_t)(m0 + r) * D_MODEL + k4);
        cp16(smem_u32(&Wb[0][r * GLD + k4]), W + (size_t)(n0 + r) * D_MODEL + k4);
    }
    CP_COMMIT;

    int cur = 0;
    for (int tt = 0; tt < nk; ++tt) {
        CP_WAIT_ALL;
        __syncthreads();
        if (tt + 1 < nk) {
            const int kp = (tt + 1) * TBK;
            #pragma unroll
            for (int c = 0; c < 4; ++c) {
                const int j  = tid + (c << 8);
                const int r  = j >> 3, k4 = (j & 7) << 2;
                cp16(smem_u32(&Ab[cur ^ 1][r * GLD + k4]), A + (size_t)(m0 + r) * D_MODEL + kp + k4);
                cp16(smem_u32(&Wb[cur ^ 1][r * GLD + k4]), W + (size_t)(n0 + r) * D_MODEL + kp + k4);
            }
            CP_COMMIT;
        }
        #pragma unroll
        for (int s8 = 0; s8 < 4; ++s8) {
            const int k0 = s8 * 8;
            uint32_t af[4][4], bf[4][2];
            #pragma unroll
            for (int mf = 0; mf < 4; ++mf) {
                const float* ab = &Ab[cur][(wm * 64 + mf * 16 + g) * GLD + k0 + t];
                af[mf][0] = __float_as_uint(ab[0]);
                af[mf][1] = __float_as_uint(ab[8 * GLD]);
                af[mf][2] = __float_as_uint(ab[4]);
                af[mf][3] = __float_as_uint(ab[8 * GLD + 4]);
            }
            #pragma unroll
            for (int nf = 0; nf < 4; ++nf) {
                const float* wb = &Wb[cur][(wn * 32 + nf * 8 + g) * GLD + k0 + t];
                bf[nf][0] = __float_as_uint(wb[0]);
                bf[nf][1] = __float_as_uint(wb[4]);
            }
            #pragma unroll
            for (int mf = 0; mf < 4; ++mf)
                #pragma unroll
                for (int nf = 0; nf < 4; ++nf)
                    mma_tf32(acc[mf][nf], af[mf], bf[nf]);
        }
        cur ^= 1;
    }

    #pragma unroll
    for (int mf = 0; mf < 4; ++mf) {
        #pragma unroll
        for (int nf = 0; nf < 4; ++nf) {
            const int n = n0 + wn * 32 + nf * 8 + 2 * t;
            const float2 bz = *(const float2*)(out.bias + n);
            #pragma unroll
            for (int h = 0; h < 2; ++h) {
                const int m = m0 + wm * 64 + mf * 16 + g + 8 * h;
                float2 r2;
                r2.x = acc[mf][nf][2 * h + 0] + bz.x;
                r2.y = acc[mf][nf][2 * h + 1] + bz.y;
                if (out.resid) {
                    const float2 rv = *(const float2*)(out.resid + (size_t)m * D_MODEL + n);
                    r2.x += rv.x; r2.y += rv.y;
                }
                if (out.round_out) { r2.x = round_tf32(r2.x); r2.y = round_tf32(r2.y); }
                *(float2*)(out.C + (size_t)m * D_MODEL + n) = r2;
            }
        }
    }
}

// fused QKV projection: grid.x in [0,24): tiles 0-7 -> q, 8-15 -> k, 16-23 -> v
__global__ __launch_bounds__(256, 2) void gemm_qkv(const float* __restrict__ xn,
                                                   const float* __restrict__ wbuf,
                                                   const float* __restrict__ bq,
                                                   const float* __restrict__ bk,
                                                   const float* __restrict__ bv,
                                                   float* __restrict__ q,
                                                   float* __restrict__ k,
                                                   float* __restrict__ v) {
    extern __shared__ float sm[];
    const int which = blockIdx.x >> 3;
    const int n0    = (blockIdx.x & 7) * TBN;
    const int m0    = blockIdx.y * TBM;
    GemmOut o;
    if (which == 0)      { o.C = q; o.bias = bq; o.round_out = 0; }
    else if (which == 1) { o.C = k; o.bias = bk; o.round_out = 0; }
    else                 { o.C = v; o.bias = bv; o.round_out = 1; }
    o.resid = nullptr;
    gemm_body(xn, wbuf + (size_t)which * D_MODEL * D_MODEL, o, m0, n0, sm);
}

// output projection with residual
__global__ __launch_bounds__(256, 2) void gemm_oproj(const float* __restrict__ att,
                                                     const float* __restrict__ Wo,
                                                     const float* __restrict__ bo,
                                                     const float* __restrict__ x,
                                                     float* __restrict__ out) {
    extern __shared__ float sm[];
    GemmOut o; o.C = out; o.bias = bo; o.resid = x; o.round_out = 0;
    gemm_body(att, Wo, o, blockIdx.y * TBM, blockIdx.x * TBN, sm);
}

// --------------------------------- RoPE (tf32-rounded out) --------------------------
__global__ __launch_bounds__(256) void rope_kernel(float* __restrict__ q, float* __restrict__ k) {
    const int idx = blockIdx.x * blockDim.x + threadIdx.x;
    const int t   = idx >> 9;
    const int rem = idx & 511;
    const int h   = rem >> 5;
    const int j   = rem & 31;
    const int n   = t & (SEQ - 1);

    const float inv = expf(-(float)(2 * j) * (9.210340371976184f / 64.f));
    float sn, cs;
    sincosf((float)n * inv, &sn, &cs);

    const size_t base = (size_t)t * D_MODEL + h * HEAD_DIM + 2 * j;
    const float q0 = q[base], q1 = q[base + 1];
    q[base]     = round_tf32(q0 * cs - q1 * sn);
    q[base + 1] = round_tf32(q0 * sn + q1 * cs);
    const float k0 = k[base], k1 = k[base + 1];
    k[base]     = round_tf32(k0 * cs - k1 * sn);
    k[base + 1] = round_tf32(k0 * sn + k1 * cs);
}

// ------------------------ flash attention, TF32 tensor cores ------------------------
// q-tile 128, k-tile 64, hd 64. 8 warps, each owns 16 q rows. Inputs pre-rounded ->
// raw bit loads everywhere, zero cvt in loops.
#define AQ  128
#define AKT 64
#define ALD 68
#define NT  (SEQ / AKT)  // 32
#define ATT_SMEM ((128*ALD + 64*ALD + 64*ALD + 128*ALD) * 4)

__global__ __launch_bounds__(256, 2) void attn_tc(const float* __restrict__ qg,
                                                  const float* __restrict__ kg,
                                                  const float* __restrict__ vg,
                                                  float* __restrict__ og) {
    extern __shared__ float sm[];
    float*    Qs  = sm;                                   // [128][68]
    float*    Ks  = Qs + 128 * ALD;                       // [64][68] rows=key
    uint32_t* Vst = (uint32_t*)(Ks + 64 * ALD);           // [64(d)][68(key)] transposed
    uint32_t* Ps  = (uint32_t*)(Vst + 64 * ALD);          // [128(q)][68(key)]

    const int tid  = threadIdx.x, wid = tid >> 5, lane = tid & 31;
    const int g    = lane >> 2, t = lane & 3;
    const int q0   = blockIdx.x * AQ;
    const size_t cbase = (size_t)blockIdx.z * SEQ * D_MODEL + (size_t)blockIdx.y * HEAD_DIM;
    const int wrow = wid * 16;

    #pragma unroll
    for (int c = 0; c < 8; ++c) {
        const int j = tid + (c << 8);
        const int r = j >> 4, k4 = (j & 15) << 2;
        cp16(smem_u32(&Qs[r * ALD + k4]), qg + cbase + (size_t)(q0 + r) * D_MODEL + k4);
    }
    #pragma unroll
    for (int c = 0; c < 4; ++c) {
        const int j = tid + (c << 8);
        const int r = j >> 4, k4 = (j & 15) << 2;
        cp16(smem_u32(&Ks[r * ALD + k4]), kg + cbase + (size_t)r * D_MODEL + k4);
    }
    CP_COMMIT;
    #pragma unroll
    for (int c = 0; c < 4; ++c) {
        const int j = tid + (c << 8);
        const int r = j >> 4, k4 = (j & 15) << 2;
        const float4 v4 = *(const float4*)(vg + cbase + (size_t)r * D_MODEL + k4);
        Vst[(k4 + 0) * ALD + r] = __float_as_uint(v4.x);
        Vst[(k4 + 1) * ALD + r] = __float_as_uint(v4.y);
        Vst[(k4 + 2) * ALD + r] = __float_as_uint(v4.z);
        Vst[(k4 + 3) * ALD + r] = __float_as_uint(v4.w);
    }
    CP_WAIT_ALL;
    __syncthreads();

    float oacc[8][4];
    float mst[2] = { -1e30f, -1e30f }, lst[2] = { 0.f, 0.f };
    #pragma unroll
    for (int df = 0; df < 8; ++df)
        #pragma unroll
        for (int c = 0; c < 4; ++c) oacc[df][c] = 0.f;

    for (int kt = 0; kt < NT; ++kt) {
        float sacc[8][4];
        #pragma unroll
        for (int nf = 0; nf < 8; ++nf)
            #pragma unroll
            for (int c = 0; c < 4; ++c) sacc[nf][c] = 0.f;

        #pragma unroll
        for (int s8 = 0; s8 < 8; ++s8) {
            const int k0 = s8 * 8;
            uint32_t af[4];
            const float* qb = &Qs[(wrow + g) * ALD + k0 + t];
            af[0] = __float_as_uint(qb[0]);
            af[1] = __float_as_uint(qb[8 * ALD]);
            af[2] = __float_as_uint(qb[4]);
            af[3] = __float_as_uint(qb[8 * ALD + 4]);
            #pragma unroll
            for (int nf = 0; nf < 8; ++nf) {
                uint32_t bf[2];
                const float* kb = &Ks[(nf * 8 + g) * ALD + k0 + t];
                bf[0] = __float_as_uint(kb[0]);
                bf[1] = __float_as_uint(kb[4]);
                mma_tf32(sacc[nf], af, bf);
            }
        }

        #pragma unroll
        for (int h = 0; h < 2; ++h) {
            float rm = -1e30f;
            #pragma unroll
            for (int nf = 0; nf < 8; ++nf)
                rm = fmaxf(rm, fmaxf(sacc[nf][2 * h], sacc[nf][2 * h + 1]));
            rm *= 0.125f;
            rm = fmaxf(rm, __shfl_xor_sync(0xffffffffu, rm, 1));
            rm = fmaxf(rm, __shfl_xor_sync(0xffffffffu, rm, 2));
            const float mnew = fmaxf(mst[h], rm);
            const float corr = __expf(mst[h] - mnew);
            float ps = 0.f;
            const int prow = wrow + g + 8 * h;
            #pragma unroll
            for (int nf = 0; nf < 8; ++nf) {
                const float p0 = __expf(sacc[nf][2 * h] * 0.125f - mnew);
                const float p1 = __expf(sacc[nf][2 * h + 1] * 0.125f - mnew);
                ps += p0 + p1;
                uint2 pu; pu.x = __float_as_uint(p0); pu.y = __float_as_uint(p1);
                *(uint2*)&Ps[prow * ALD + nf * 8 + 2 * t] = pu;
            }
            ps += __shfl_xor_sync(0xffffffffu, ps, 1);
            ps += __shfl_xor_sync(0xffffffffu, ps, 2);
            lst[h] = lst[h] * corr + ps;
            mst[h] = mnew;
            #pragma unroll
            for (int df = 0; df < 8; ++df) {
                oacc[df][2 * h]     *= corr;
                oacc[df][2 * h + 1] *= corr;
            }
        }
        __syncwarp();

        __syncthreads();
        if (kt + 1 < NT) {
            #pragma unroll
            for (int c = 0; c < 4; ++c) {
                const int j = tid + (c << 8);
                const int r = j >> 4, k4 = (j & 15) << 2;
                cp16(smem_u32(&Ks[r * ALD + k4]),
                     kg + cbase + (size_t)((kt + 1) * AKT + r) * D_MODEL + k4);
            }
            CP_COMMIT;
        }

        #pragma unroll
        for (int s8 = 0; s8 < 8; ++s8) {
            const int k0 = s8 * 8;
            uint32_t af[4];
            const uint32_t* pb = &Ps[(wrow + g) * ALD + k0 + t];
            af[0] = pb[0];
            af[1] = pb[8 * ALD];
            af[2] = pb[4];
            af[3] = pb[8 * ALD + 4];
            #pragma unroll
            for (int df = 0; df < 8; ++df) {
                uint32_t bf[2];
                bf[0] = Vst[(df * 8 + g) * ALD + k0 + t];
                bf[1] = Vst[(df * 8 + g) * ALD + k0 + t + 4];
                mma_tf32(oacc[df], af, bf);
            }
        }

        __syncthreads();
        if (kt + 1 < NT) {
            #pragma unroll
            for (int c = 0; c < 4; ++c) {
                const int j = tid + (c << 8);
                const int r = j >> 4, k4 = (j & 15) << 2;
                const float4 v4 = *(const float4*)(vg + cbase +
                                   (size_t)((kt + 1) * AKT + r) * D_MODEL + k4);
                Vst[(k4 + 0) * ALD + r] = __float_as_uint(v4.x);
                Vst[(k4 + 1) * ALD + r] = __float_as_uint(v4.y);
                Vst[(k4 + 2) * ALD + r] = __float_as_uint(v4.z);
                Vst[(k4 + 3) * ALD + r] = __float_as_uint(v4.w);
            }
            CP_WAIT_ALL;
        }
        __syncthreads();
    }

    // finalize: divide by l, tf32-round (att feeds the o-proj GEMM raw loads)
    #pragma unroll
    for (int h = 0; h < 2; ++h) {
        const float inv = 1.f / lst[h];
        const int row = q0 + wrow + g + 8 * h;
        #pragma unroll
        for (int df = 0; df < 8; ++df) {
            float2 o2;
            o2.x = round_tf32(oacc[df][2 * h]     * inv);
            o2.y = round_tf32(oacc[df][2 * h + 1] * inv);
            *(float2*)(og + cbase + (size_t)row * D_MODEL + df * 8 + 2 * t) = o2;
        }
    }
}

// ---------------------------------- launch ------------------------------------------
extern "C" void kernel_launch(void* const* d_in, const int* in_sizes, int n_in,
                              void* d_out, int out_size) {
    const float* x    = (const float*)d_in[0];
    const float* ln_w = (const float*)d_in[1];
    const float* ln_b = (const float*)d_in[2];
    const float* Wq   = (const float*)d_in[3];
    const float* bq   = (const float*)d_in[4];
    const float* Wk   = (const float*)d_in[5];
    const float* bk   = (const float*)d_in[6];
    const float* Wv   = (const float*)d_in[7];
    const float* bv   = (const float*)d_in[8];
    const float* Wo   = (const float*)d_in[9];
    const float* bo   = (const float*)d_in[10];
    float* out = (float*)d_out;

    float *xn, *q, *k, *v, *att, *wbuf;
    cudaGetSymbolAddress((void**)&xn,  g_xn);
    cudaGetSymbolAddress((void**)&q,   g_q);
    cudaGetSymbolAddress((void**)&k,   g_k);
    cudaGetSymbolAddress((void**)&v,   g_v);
    cudaGetSymbolAddress((void**)&att, g_att);
    cudaGetSymbolAddress((void**)&wbuf, g_w);
    const int WN = D_MODEL * D_MODEL;

    round_w_kernel<<<WN / 4 / 256, 256>>>(Wq, Wk, Wv, Wo, wbuf);
    ln_kernel<<<NTOK, 256>>>(x, ln_w, ln_b, xn);

    cudaFuncSetAttribute(gemm_qkv,   cudaFuncAttributeMaxDynamicSharedMemorySize, GEMM_SMEM);
    cudaFuncSetAttribute(gemm_oproj, cudaFuncAttributeMaxDynamicSharedMemorySize, GEMM_SMEM);

    gemm_qkv<<<dim3(24, NTOK / TBM), 256, GEMM_SMEM>>>(xn, wbuf, bq, bk, bv, q, k, v);

    rope_kernel<<<(NTOK * 512) / 256, 256>>>(q, k);

    cudaFuncSetAttribute(attn_tc, cudaFuncAttributeMaxDynamicSharedMemorySize, ATT_SMEM);
    attn_tc<<<dim3(SEQ / AQ, NHEAD, BATCH), 256, ATT_SMEM>>>(q, k, v, att);

    gemm_oproj<<<dim3(D_MODEL / TBN, NTOK / TBM), 256, GEMM_SMEM>>>(att, wbuf + 3 * WN, bo, x, out);
}

// round 5
// speedup vs baseline: 5.8680x; 2.2532x over previous
#include <cuda_runtime.h>
#include <cuda_bf16.h>
#include <math.h>
#include <stdint.h>

#define D_MODEL 1024
#define NHEAD   16
#define HEAD_DIM 64
#define BATCH   2
#define SEQ     2048
#define NTOK    (BATCH * SEQ)   // 4096

// ------------------------- scratch (no allocations allowed) -------------------------
__device__ __nv_bfloat16 g_xn [NTOK * D_MODEL];
__device__ __nv_bfloat16 g_q  [NTOK * D_MODEL];
__device__ __nv_bfloat16 g_k  [NTOK * D_MODEL];
__device__ __nv_bfloat16 g_v  [NTOK * D_MODEL];
__device__ __nv_bfloat16 g_att[NTOK * D_MODEL];
__device__ __nv_bfloat16 g_w  [4 * D_MODEL * D_MODEL];   // bf16 Wq,Wk,Wv,Wo

// ------------------------------- helpers --------------------------------------------
__device__ __forceinline__ void mma_bf16(float* d, const uint32_t* a, const uint32_t* b) {
    asm volatile(
        "mma.sync.aligned.m16n8k16.row.col.f32.bf16.bf16.f32 "
        "{%0,%1,%2,%3}, {%4,%5,%6,%7}, {%8,%9}, {%0,%1,%2,%3};"
        : "+f"(d[0]), "+f"(d[1]), "+f"(d[2]), "+f"(d[3])
        : "r"(a[0]), "r"(a[1]), "r"(a[2]), "r"(a[3]), "r"(b[0]), "r"(b[1]));
}
__device__ __forceinline__ void ldm4(uint32_t* r, uint32_t a) {
    asm volatile("ldmatrix.sync.aligned.m8n8.x4.shared.b16 {%0,%1,%2,%3}, [%4];"
        : "=r"(r[0]), "=r"(r[1]), "=r"(r[2]), "=r"(r[3]) : "r"(a));
}
__device__ __forceinline__ void ldm4t(uint32_t* r, uint32_t a) {
    asm volatile("ldmatrix.sync.aligned.m8n8.x4.trans.shared.b16 {%0,%1,%2,%3}, [%4];"
        : "=r"(r[0]), "=r"(r[1]), "=r"(r[2]), "=r"(r[3]) : "r"(a));
}
__device__ __forceinline__ uint32_t smem_u32(const void* p) {
    return (uint32_t)__cvta_generic_to_shared(p);
}
__device__ __forceinline__ void cp16(uint32_t s, const void* g) {
    asm volatile("cp.async.cg.shared.global [%0], [%1], 16;" :: "r"(s), "l"(g));
}
#define CP_COMMIT   asm volatile("cp.async.commit_group;")
#define CP_WAIT_ALL asm volatile("cp.async.wait_all;")

// ------------------------------- weight pre-round to bf16 ---------------------------
__global__ __launch_bounds__(256) void round_w_kernel(const float* __restrict__ a,
                                                      const float* __restrict__ b,
                                                      const float* __restrict__ c,
                                                      const float* __restrict__ d,
                                                      __nv_bfloat16* __restrict__ o) {
    const int i = blockIdx.x * 256 + threadIdx.x;          // float4 index
    const int n4 = D_MODEL * D_MODEL / 4;
    const float4 va = reinterpret_cast<const float4*>(a)[i];
    const float4 vb = reinterpret_cast<const float4*>(b)[i];
    const float4 vc = reinterpret_cast<const float4*>(c)[i];
    const float4 vd = reinterpret_cast<const float4*>(d)[i];
    uint2 u;
    __nv_bfloat162 h0, h1;
    h0 = __floats2bfloat162_rn(va.x, va.y); h1 = __floats2bfloat162_rn(va.z, va.w);
    u.x = *(uint32_t*)&h0; u.y = *(uint32_t*)&h1;
    *(uint2*)(o + (size_t)i * 4) = u;
    h0 = __floats2bfloat162_rn(vb.x, vb.y); h1 = __floats2bfloat162_rn(vb.z, vb.w);
    u.x = *(uint32_t*)&h0; u.y = *(uint32_t*)&h1;
    *(uint2*)(o + (size_t)(n4 + i) * 4) = u;
    h0 = __floats2bfloat162_rn(vc.x, vc.y); h1 = __floats2bfloat162_rn(vc.z, vc.w);
    u.x = *(uint32_t*)&h0; u.y = *(uint32_t*)&h1;
    *(uint2*)(o + (size_t)(2 * n4 + i) * 4) = u;
    h0 = __floats2bfloat162_rn(vd.x, vd.y); h1 = __floats2bfloat162_rn(vd.z, vd.w);
    u.x = *(uint32_t*)&h0; u.y = *(uint32_t*)&h1;
    *(uint2*)(o + (size_t)(3 * n4 + i) * 4) = u;
}

// ------------------------------- LayerNorm (bf16 out) -------------------------------
__global__ __launch_bounds__(256) void ln_kernel(const float* __restrict__ x,
                                                 const float* __restrict__ w,
                                                 const float* __restrict__ b,
                                                 __nv_bfloat16* __restrict__ y) {
    const int t   = blockIdx.x;
    const int tid = threadIdx.x;
    const float4* xr = reinterpret_cast<const float4*>(x + (size_t)t * D_MODEL);
    float4 v = xr[tid];

    __shared__ float red[8];
    float s = v.x + v.y + v.z + v.w;
    #pragma unroll
    for (int m = 16; m >= 1; m >>= 1) s += __shfl_xor_sync(0xffffffffu, s, m);
    if ((tid & 31) == 0) red[tid >> 5] = s;
    __syncthreads();
    float tot = 0.f;
    #pragma unroll
    for (int i = 0; i < 8; ++i) tot += red[i];
    const float mu = tot * (1.0f / D_MODEL);
    __syncthreads();

    const float dx = v.x - mu, dy = v.y - mu, dz = v.z - mu, dw = v.w - mu;
    float sq = dx*dx + dy*dy + dz*dz + dw*dw;
    #pragma unroll
    for (int m = 16; m >= 1; m >>= 1) sq += __shfl_xor_sync(0xffffffffu, sq, m);
    if ((tid & 31) == 0) red[tid >> 5] = sq;
    __syncthreads();
    float tot2 = 0.f;
    #pragma unroll
    for (int i = 0; i < 8; ++i) tot2 += red[i];
    const float rstd = rsqrtf(tot2 * (1.0f / D_MODEL) + 1e-5f);

    const float4 wv = reinterpret_cast<const float4*>(w)[tid];
    const float4 bv = reinterpret_cast<const float4*>(b)[tid];
    __nv_bfloat162 h0 = __floats2bfloat162_rn(dx * rstd * wv.x + bv.x, dy * rstd * wv.y + bv.y);
    __nv_bfloat162 h1 = __floats2bfloat162_rn(dz * rstd * wv.z + bv.z, dw * rstd * wv.w + bv.w);
    uint2 u; u.x = *(uint32_t*)&h0; u.y = *(uint32_t*)&h1;
    *(uint2*)(y + (size_t)t * D_MODEL + tid * 4) = u;
}

// ------------------------- bf16 tensor-core GEMM: C = A * W^T (+bias)(+resid) -------
// A: [M,K] bf16 row-major, W: [N,K] bf16 row-major. 128x128x64 tiles, double buffer.
// smem rows stride 72 bf16 = 144B: ldmatrix conflict-free, cp.async 16B aligned.
#define TBM 128
#define TBN 128
#define BST 72
#define GSTG 18432                         // bytes, one matrix one stage (128*144)
#define GEMM_SMEM (4 * GSTG)               // A0 W0 A1 W1

struct GemmOut {
    void* C;
    const float* bias;
    const float* resid;
    int bf16_out;
};

__device__ __forceinline__ void gemm_body(const __nv_bfloat16* __restrict__ A,
                                          const __nv_bfloat16* __restrict__ W,
                                          const GemmOut& out,
                                          int m0, int n0, char* smem) {
    const uint32_t sb = smem_u32(smem);
    const int tid  = threadIdx.x;
    const int wid  = tid >> 5, lane = tid & 31;
    const int wm   = wid >> 2, wn   = wid & 3;     // 2 x 4 warps, warp tile 64x32
    const int g    = lane >> 2, t   = lane & 3;

    float acc[4][4][4];
    #pragma unroll
    for (int a = 0; a < 4; ++a)
        #pragma unroll
        for (int b = 0; b < 4; ++b)
            #pragma unroll
            for (int c = 0; c < 4; ++c) acc[a][b][c] = 0.f;

    // ldmatrix lane address components
    const uint32_t a_row = (uint32_t)(lane & 15);
    const uint32_t a_cb  = (uint32_t)((lane >> 4) << 4);
    const uint32_t b_row = (uint32_t)((lane & 7) + ((lane >> 4) << 3));
    const uint32_t b_cb  = (uint32_t)(((lane >> 3) & 1) << 4);

    #define GF(s_, kt_) do {                                                        \
        const int kk_ = (kt_) * 64;                                                 \
        _Pragma("unroll")                                                           \
        for (int c_ = 0; c_ < 4; ++c_) {                                            \
            const int j_ = tid + (c_ << 8);                                         \
            const int r_ = j_ >> 3, cc_ = j_ & 7;                                   \
            cp16(sb + (s_) * 2 * GSTG + r_ * 144 + cc_ * 16,                        \
                 A + (size_t)(m0 + r_) * D_MODEL + kk_ + cc_ * 8);                  \
            cp16(sb + (s_) * 2 * GSTG + GSTG + r_ * 144 + cc_ * 16,                 \
                 W + (size_t)(n0 + r_) * D_MODEL + kk_ + cc_ * 8);                  \
        }                                                                           \
    } while (0)

    GF(0, 0);
    CP_COMMIT;

    int cur = 0;
    #pragma unroll 1
    for (int tt = 0; tt < D_MODEL / 64; ++tt) {
        CP_WAIT_ALL;
        __syncthreads();
        if (tt + 1 < D_MODEL / 64) {
            GF(cur ^ 1, tt + 1);
            CP_COMMIT;
        }
        const uint32_t ab = sb + cur * 2 * GSTG;
        const uint32_t wb = ab + GSTG;
        #pragma unroll
        for (int s16 = 0; s16 < 4; ++s16) {
            const uint32_t kb = s16 * 32;
            uint32_t af[4][4], bf[4][4];
            #pragma unroll
            for (int mf = 0; mf < 4; ++mf)
                ldm4(af[mf], ab + (wm * 64 + mf * 16 + a_row) * 144 + a_cb + kb);
            #pragma unroll
            for (int nfp = 0; nfp < 2; ++nfp)
                ldm4(bf[nfp * 2], wb + (wn * 32 + nfp * 16 + b_row) * 144 + b_cb + kb);
            #pragma unroll
            for (int mf = 0; mf < 4; ++mf) {
                mma_bf16(acc[mf][0], af[mf], &bf[0][0]);
                mma_bf16(acc[mf][1], af[mf], &bf[0][2]);
                mma_bf16(acc[mf][2], af[mf], &bf[2][0]);
                mma_bf16(acc[mf][3], af[mf], &bf[2][2]);
            }
        }
        cur ^= 1;
    }
    #undef GF

    #pragma unroll
    for (int mf = 0; mf < 4; ++mf) {
        #pragma unroll
        for (int nf = 0; nf < 4; ++nf) {
            const int n = n0 + wn * 32 + nf * 8 + 2 * t;
            const float2 bz = *(const float2*)(out.bias + n);
            #pragma unroll
            for (int h = 0; h < 2; ++h) {
                const int m = m0 + wm * 64 + mf * 16 + g + 8 * h;
                float2 r2;
                r2.x = acc[mf][nf][2 * h + 0] + bz.x;
                r2.y = acc[mf][nf][2 * h + 1] + bz.y;
                if (out.resid) {
                    const float2 rv = *(const float2*)(out.resid + (size_t)m * D_MODEL + n);
                    r2.x += rv.x; r2.y += rv.y;
                }
                if (out.bf16_out) {
                    __nv_bfloat162 hh = __floats2bfloat162_rn(r2.x, r2.y);
                    *(__nv_bfloat162*)((__nv_bfloat16*)out.C + (size_t)m * D_MODEL + n) = hh;
                } else {
                    *(float2*)((float*)out.C + (size_t)m * D_MODEL + n) = r2;
                }
            }
        }
    }
}

// fused QKV: grid.x in [0,24): tiles 0-7 -> q, 8-15 -> k, 16-23 -> v
__global__ __launch_bounds__(256, 2) void gemm_qkv(const __nv_bfloat16* __restrict__ xn,
                                                   const __nv_bfloat16* __restrict__ wbuf,
                                                   const float* __restrict__ bq,
                                                   const float* __restrict__ bk,
                                                   const float* __restrict__ bv,
                                                   __nv_bfloat16* __restrict__ q,
                                                   __nv_bfloat16* __restrict__ k,
                                                   __nv_bfloat16* __restrict__ v) {
    extern __shared__ char smc[];
    const int which = blockIdx.x >> 3;
    const int n0    = (blockIdx.x & 7) * TBN;
    const int m0    = blockIdx.y * TBM;
    GemmOut o;
    if (which == 0)      { o.C = q; o.bias = bq; }
    else if (which == 1) { o.C = k; o.bias = bk; }
    else                 { o.C = v; o.bias = bv; }
    o.resid = nullptr; o.bf16_out = 1;
    gemm_body(xn, wbuf + (size_t)which * D_MODEL * D_MODEL, o, m0, n0, smc);
}

__global__ __launch_bounds__(256, 2) void gemm_oproj(const __nv_bfloat16* __restrict__ att,
                                                     const __nv_bfloat16* __restrict__ Wo,
                                                     const float* __restrict__ bo,
                                                     const float* __restrict__ x,
                                                     float* __restrict__ out) {
    extern __shared__ char smc[];
    GemmOut o; o.C = out; o.bias = bo; o.resid = x; o.bf16_out = 0;
    gemm_body(att, Wo, o, blockIdx.y * TBM, blockIdx.x * TBN, smc);
}

// --------------------------------- RoPE (bf16 in/out) -------------------------------
__global__ __launch_bounds__(256) void rope_kernel(__nv_bfloat16* __restrict__ q,
                                                   __nv_bfloat16* __restrict__ k) {
    const int idx = blockIdx.x * blockDim.x + threadIdx.x;
    const int t   = idx >> 9;
    const int rem = idx & 511;
    const int h   = rem >> 5;
    const int j   = rem & 31;
    const int n   = t & (SEQ - 1);

    const float inv = expf(-(float)(2 * j) * (9.210340371976184f / 64.f));
    float sn, cs;
    sincosf((float)n * inv, &sn, &cs);

    const size_t base = (size_t)t * D_MODEL + h * HEAD_DIM + 2 * j;
    __nv_bfloat162 qv = *(__nv_bfloat162*)(q + base);
    const float q0 = __bfloat162float(qv.x), q1 = __bfloat162float(qv.y);
    *(__nv_bfloat162*)(q + base) = __floats2bfloat162_rn(q0 * cs - q1 * sn, q0 * sn + q1 * cs);
    __nv_bfloat162 kv = *(__nv_bfloat162*)(k + base);
    const float k0 = __bfloat162float(kv.x), k1 = __bfloat162float(kv.y);
    *(__nv_bfloat162*)(k + base) = __floats2bfloat162_rn(k0 * cs - k1 * sn, k0 * sn + k1 * cs);
}

// ------------------------ flash attention, bf16 tensor cores ------------------------
// q-tile 128, k-tile 64, hd 64. 8 warps x 16 q-rows. All fragments via ldmatrix.
#define AQ  128
#define AKT 64
#define NT  (SEQ / AKT)  // 32
#define QS_B (128 * 144)
#define KS_B (64 * 144)
#define VS_B (64 * 144)
#define PS_B (128 * 144)
#define ATT_SMEM (QS_B + KS_B + VS_B + PS_B)   // 55296

__global__ __launch_bounds__(256, 2) void attn_tc(const __nv_bfloat16* __restrict__ qg,
                                                  const __nv_bfloat16* __restrict__ kg,
                                                  const __nv_bfloat16* __restrict__ vg,
                                                  __nv_bfloat16* __restrict__ og) {
    extern __shared__ char smc[];
    const uint32_t sb   = smem_u32(smc);
    const uint32_t qoff = sb;
    const uint32_t koff = sb + QS_B;
    const uint32_t voff = koff + KS_B;
    const uint32_t poff = voff + VS_B;
    __nv_bfloat16* Psp = (__nv_bfloat16*)(smc + QS_B + KS_B + VS_B);

    const int tid  = threadIdx.x, wid = tid >> 5, lane = tid & 31;
    const int g    = lane >> 2, t = lane & 3;
    const int q0   = blockIdx.x * AQ;
    const size_t cbase = (size_t)blockIdx.z * SEQ * D_MODEL + (size_t)blockIdx.y * HEAD_DIM;
    const int wrow = wid * 16;

    const uint32_t a_row = (uint32_t)(lane & 15);
    const uint32_t a_cb  = (uint32_t)((lane >> 4) << 4);
    const uint32_t b_row = (uint32_t)((lane & 7) + ((lane >> 4) << 3));
    const uint32_t b_cb  = (uint32_t)(((lane >> 3) & 1) << 4);

    // ---- prologue: Q (1024 chunks), K,V (512 chunks each) ----
    #pragma unroll
    for (int c = 0; c < 4; ++c) {
        const int j = tid + (c << 8);
        const int r = j >> 3, cc = j & 7;
        cp16(qoff + r * 144 + cc * 16, qg + cbase + (size_t)(q0 + r) * D_MODEL + cc * 8);
    }
    #pragma unroll
    for (int c = 0; c < 2; ++c) {
        const int j = tid + (c << 8);
        const int r = j >> 3, cc = j & 7;
        cp16(koff + r * 144 + cc * 16, kg + cbase + (size_t)r * D_MODEL + cc * 8);
        cp16(voff + r * 144 + cc * 16, vg + cbase + (size_t)r * D_MODEL + cc * 8);
    }
    CP_COMMIT;
    CP_WAIT_ALL;
    __syncthreads();

    float oacc[8][4];
    float mst[2] = { -1e30f, -1e30f }, lst[2] = { 0.f, 0.f };
    #pragma unroll
    for (int df = 0; df < 8; ++df)
        #pragma unroll
        for (int c = 0; c < 4; ++c) oacc[df][c] = 0.f;

    #pragma unroll 1
    for (int kt = 0; kt < NT; ++kt) {
        // ---- S = Q K^T ----
        float sacc[8][4];
        #pragma unroll
        for (int nf = 0; nf < 8; ++nf)
            #pragma unroll
            for (int c = 0; c < 4; ++c) sacc[nf][c] = 0.f;

        #pragma unroll
        for (int s16 = 0; s16 < 4; ++s16) {
            const uint32_t kb = s16 * 32;
            uint32_t af[4];
            ldm4(af, qoff + (wrow + a_row) * 144 + a_cb + kb);
            #pragma unroll
            for (int nfp = 0; nfp < 4; ++nfp) {
                uint32_t t4[4];
                ldm4(t4, koff + (nfp * 16 + b_row) * 144 + b_cb + kb);
                mma_bf16(sacc[nfp * 2],     af, &t4[0]);
                mma_bf16(sacc[nfp * 2 + 1], af, &t4[2]);
            }
        }

        // ---- online softmax (rows g, g+8; reduce over 4 lanes of thread-row) ----
        #pragma unroll
        for (int h = 0; h < 2; ++h) {
            float rm = -1e30f;
            #pragma unroll
            for (int nf = 0; nf < 8; ++nf)
                rm = fmaxf(rm, fmaxf(sacc[nf][2 * h], sacc[nf][2 * h + 1]));
            rm *= 0.125f;
            rm = fmaxf(rm, __shfl_xor_sync(0xffffffffu, rm, 1));
            rm = fmaxf(rm, __shfl_xor_sync(0xffffffffu, rm, 2));
            const float mnew = fmaxf(mst[h], rm);
            const float corr = __expf(mst[h] - mnew);
            float ps = 0.f;
            const int prow = wrow + g + 8 * h;
            #pragma unroll
            for (int nf = 0; nf < 8; ++nf) {
                const float p0 = __expf(sacc[nf][2 * h] * 0.125f - mnew);
                const float p1 = __expf(sacc[nf][2 * h + 1] * 0.125f - mnew);
                ps += p0 + p1;
                *(__nv_bfloat162*)&Psp[prow * BST + nf * 8 + 2 * t] = __floats2bfloat162_rn(p0, p1);
            }
            ps += __shfl_xor_sync(0xffffffffu, ps, 1);
            ps += __shfl_xor_sync(0xffffffffu, ps, 2);
            lst[h] = lst[h] * corr + ps;
            mst[h] = mnew;
            #pragma unroll
            for (int df = 0; df < 8; ++df) {
                oacc[df][2 * h]     *= corr;
                oacc[df][2 * h + 1] *= corr;
            }
        }
        __syncwarp();

        __syncthreads();   // all warps done reading Ks
        if (kt + 1 < NT) { // overlap K(kt+1) with PV
            #pragma unroll
            for (int c = 0; c < 2; ++c) {
                const int j = tid + (c << 8);
                const int r = j >> 3, cc = j & 7;
                cp16(koff + r * 144 + cc * 16,
                     kg + cbase + (size_t)((kt + 1) * AKT + r) * D_MODEL + cc * 8);
            }
            CP_COMMIT;
        }

        // ---- O += P V ----
        #pragma unroll
        for (int s16 = 0; s16 < 4; ++s16) {
            const uint32_t kb = s16 * 32;
            uint32_t af[4];
            ldm4(af, poff + (wrow + a_row) * 144 + a_cb + kb);
            #pragma unroll
            for (int nfp = 0; nfp < 4; ++nfp) {
                uint32_t t4[4];
                ldm4t(t4, voff + (s16 * 16 + a_row) * 144 + a_cb + nfp * 32);
                mma_bf16(oacc[nfp * 2],     af, &t4[0]);
                mma_bf16(oacc[nfp * 2 + 1], af, &t4[2]);
            }
        }

        __syncthreads();   // all warps done reading Vs
        if (kt + 1 < NT) {
            #pragma unroll
            for (int c = 0; c < 2; ++c) {
                const int j = tid + (c << 8);
                const int r = j >> 3, cc = j & 7;
                cp16(voff + r * 144 + cc * 16,
                     vg + cbase + (size_t)((kt + 1) * AKT + r) * D_MODEL + cc * 8);
            }
            CP_COMMIT;
            CP_WAIT_ALL;
        }
        __syncthreads();
    }

    // ---- finalize: /l, bf16 out (feeds o-proj GEMM) ----
    #pragma unroll
    for (int h = 0; h < 2; ++h) {
        const float inv = 1.f / lst[h];
        const int row = q0 + wrow + g + 8 * h;
        #pragma unroll
        for (int df = 0; df < 8; ++df) {
            __nv_bfloat162 o2 = __floats2bfloat162_rn(oacc[df][2 * h] * inv,
                                                      oacc[df][2 * h + 1] * inv);
            *(__nv_bfloat162*)(og + cbase + (size_t)row * D_MODEL + df * 8 + 2 * t) = o2;
        }
    }
}

// ---------------------------------- launch ------------------------------------------
extern "C" void kernel_launch(void* const* d_in, const int* in_sizes, int n_in,
                              void* d_out, int out_size) {
    const float* x    = (const float*)d_in[0];
    const float* ln_w = (const float*)d_in[1];
    const float* ln_b = (const float*)d_in[2];
    const float* Wq   = (const float*)d_in[3];
    const float* bq   = (const float*)d_in[4];
    const float* Wk   = (const float*)d_in[5];
    const float* bk   = (const float*)d_in[6];
    const float* Wv   = (const float*)d_in[7];
    const float* bv   = (const float*)d_in[8];
    const float* Wo   = (const float*)d_in[9];
    const float* bo   = (const float*)d_in[10];
    float* out = (float*)d_out;

    __nv_bfloat16 *xn, *q, *k, *v, *att, *wbuf;
    cudaGetSymbolAddress((void**)&xn,  g_xn);
    cudaGetSymbolAddress((void**)&q,   g_q);
    cudaGetSymbolAddress((void**)&k,   g_k);
    cudaGetSymbolAddress((void**)&v,   g_v);
    cudaGetSymbolAddress((void**)&att, g_att);
    cudaGetSymbolAddress((void**)&wbuf, g_w);
    const size_t WN = (size_t)D_MODEL * D_MODEL;

    round_w_kernel<<<(int)(WN / 4 / 256), 256>>>(Wq, Wk, Wv, Wo, wbuf);
    ln_kernel<<<NTOK, 256>>>(x, ln_w, ln_b, xn);

    cudaFuncSetAttribute(gemm_qkv,   cudaFuncAttributeMaxDynamicSharedMemorySize, GEMM_SMEM);
    cudaFuncSetAttribute(gemm_oproj, cudaFuncAttributeMaxDynamicSharedMemorySize, GEMM_SMEM);

    gemm_qkv<<<dim3(24, NTOK / TBM), 256, GEMM_SMEM>>>(xn, wbuf, bq, bk, bv, q, k, v);

    rope_kernel<<<(NTOK * 512) / 256, 256>>>(q, k);

    cudaFuncSetAttribute(attn_tc, cudaFuncAttributeMaxDynamicSharedMemorySize, ATT_SMEM);
    attn_tc<<<dim3(SEQ / AQ, NHEAD, BATCH), 256, ATT_SMEM>>>(q, k, v, att);

    gemm_oproj<<<dim3(D_MODEL / TBN, NTOK / TBM), 256, GEMM_SMEM>>>(att, wbuf + 3 * WN, bo, x, out);
}

// round 6
// speedup vs baseline: 6.0328x; 1.0281x over previous
#include <cuda_runtime.h>
#include <cuda_bf16.h>
#include <math.h>
#include <stdint.h>

#define D_MODEL 1024
#define NHEAD   16
#define HEAD_DIM 64
#define BATCH   2
#define SEQ     2048
#define NTOK    (BATCH * SEQ)   // 4096

// ------------------------- scratch (no allocations allowed) -------------------------
__device__ __nv_bfloat16 g_xn [NTOK * D_MODEL];
__device__ __nv_bfloat16 g_q  [NTOK * D_MODEL];
__device__ __nv_bfloat16 g_k  [NTOK * D_MODEL];
__device__ __nv_bfloat16 g_v  [NTOK * D_MODEL];
__device__ __nv_bfloat16 g_att[NTOK * D_MODEL];
__device__ __nv_bfloat16 g_w  [4 * D_MODEL * D_MODEL];   // bf16 Wq,Wk,Wv,Wo
__device__ float2        g_rope[SEQ * 32];               // cos/sin table

// ------------------------------- helpers --------------------------------------------
__device__ __forceinline__ void mma_bf16(float* d, const uint32_t* a, const uint32_t* b) {
    asm volatile(
        "mma.sync.aligned.m16n8k16.row.col.f32.bf16.bf16.f32 "
        "{%0,%1,%2,%3}, {%4,%5,%6,%7}, {%8,%9}, {%0,%1,%2,%3};"
        : "+f"(d[0]), "+f"(d[1]), "+f"(d[2]), "+f"(d[3])
        : "r"(a[0]), "r"(a[1]), "r"(a[2]), "r"(a[3]), "r"(b[0]), "r"(b[1]));
}
__device__ __forceinline__ void ldm4(uint32_t* r, uint32_t a) {
    asm volatile("ldmatrix.sync.aligned.m8n8.x4.shared.b16 {%0,%1,%2,%3}, [%4];"
        : "=r"(r[0]), "=r"(r[1]), "=r"(r[2]), "=r"(r[3]) : "r"(a));
}
__device__ __forceinline__ void ldm4t(uint32_t* r, uint32_t a) {
    asm volatile("ldmatrix.sync.aligned.m8n8.x4.trans.shared.b16 {%0,%1,%2,%3}, [%4];"
        : "=r"(r[0]), "=r"(r[1]), "=r"(r[2]), "=r"(r[3]) : "r"(a));
}
__device__ __forceinline__ uint32_t smem_u32(const void* p) {
    return (uint32_t)__cvta_generic_to_shared(p);
}
__device__ __forceinline__ void cp16(uint32_t s, const void* g) {
    asm volatile("cp.async.cg.shared.global [%0], [%1], 16;" :: "r"(s), "l"(g));
}
#define CP_COMMIT   asm volatile("cp.async.commit_group;")
#define CP_WAIT_ALL asm volatile("cp.async.wait_all;")
#define CP_WAIT_GROUP(n) asm volatile("cp.async.wait_group %0;" :: "n"(n))

// ------------------------------- rope table -----------------------------------------
__global__ __launch_bounds__(256) void rope_table_kernel(float2* __restrict__ tab) {
    const int idx = blockIdx.x * 256 + threadIdx.x;   // < SEQ*32
    const int pos = idx >> 5, j = idx & 31;
    const float inv = expf(-(float)(2 * j) * (9.210340371976184f / 64.f));
    float sn, cs;
    sincosf((float)pos * inv, &sn, &cs);
    tab[idx] = make_float2(cs, sn);
}

// ------------------------------- weight pre-round to bf16 ---------------------------
__global__ __launch_bounds__(256) void round_w_kernel(const float* __restrict__ a,
                                                      const float* __restrict__ b,
                                                      const float* __restrict__ c,
                                                      const float* __restrict__ d,
                                                      __nv_bfloat16* __restrict__ o) {
    const int i = blockIdx.x * 256 + threadIdx.x;          // float4 index
    const int n4 = D_MODEL * D_MODEL / 4;
    const float4 va = reinterpret_cast<const float4*>(a)[i];
    const float4 vb = reinterpret_cast<const float4*>(b)[i];
    const float4 vc = reinterpret_cast<const float4*>(c)[i];
    const float4 vd = reinterpret_cast<const float4*>(d)[i];
    uint2 u;
    __nv_bfloat162 h0, h1;
    h0 = __floats2bfloat162_rn(va.x, va.y); h1 = __floats2bfloat162_rn(va.z, va.w);
    u.x = *(uint32_t*)&h0; u.y = *(uint32_t*)&h1;
    *(uint2*)(o + (size_t)i * 4) = u;
    h0 = __floats2bfloat162_rn(vb.x, vb.y); h1 = __floats2bfloat162_rn(vb.z, vb.w);
    u.x = *(uint32_t*)&h0; u.y = *(uint32_t*)&h1;
    *(uint2*)(o + (size_t)(n4 + i) * 4) = u;
    h0 = __floats2bfloat162_rn(vc.x, vc.y); h1 = __floats2bfloat162_rn(vc.z, vc.w);
    u.x = *(uint32_t*)&h0; u.y = *(uint32_t*)&h1;
    *(uint2*)(o + (size_t)(2 * n4 + i) * 4) = u;
    h0 = __floats2bfloat162_rn(vd.x, vd.y); h1 = __floats2bfloat162_rn(vd.z, vd.w);
    u.x = *(uint32_t*)&h0; u.y = *(uint32_t*)&h1;
    *(uint2*)(o + (size_t)(3 * n4 + i) * 4) = u;
}

// ------------------------------- LayerNorm (bf16 out) -------------------------------
__global__ __launch_bounds__(256) void ln_kernel(const float* __restrict__ x,
                                                 const float* __restrict__ w,
                                                 const float* __restrict__ b,
                                                 __nv_bfloat16* __restrict__ y) {
    const int t   = blockIdx.x;
    const int tid = threadIdx.x;
    const float4* xr = reinterpret_cast<const float4*>(x + (size_t)t * D_MODEL);
    float4 v = xr[tid];

    __shared__ float red[8];
    float s = v.x + v.y + v.z + v.w;
    #pragma unroll
    for (int m = 16; m >= 1; m >>= 1) s += __shfl_xor_sync(0xffffffffu, s, m);
    if ((tid & 31) == 0) red[tid >> 5] = s;
    __syncthreads();
    float tot = 0.f;
    #pragma unroll
    for (int i = 0; i < 8; ++i) tot += red[i];
    const float mu = tot * (1.0f / D_MODEL);
    __syncthreads();

    const float dx = v.x - mu, dy = v.y - mu, dz = v.z - mu, dw = v.w - mu;
    float sq = dx*dx + dy*dy + dz*dz + dw*dw;
    #pragma unroll
    for (int m = 16; m >= 1; m >>= 1) sq += __shfl_xor_sync(0xffffffffu, sq, m);
    if ((tid & 31) == 0) red[tid >> 5] = sq;
    __syncthreads();
    float tot2 = 0.f;
    #pragma unroll
    for (int i = 0; i < 8; ++i) tot2 += red[i];
    const float rstd = rsqrtf(tot2 * (1.0f / D_MODEL) + 1e-5f);

    const float4 wv = reinterpret_cast<const float4*>(w)[tid];
    const float4 bv = reinterpret_cast<const float4*>(b)[tid];
    __nv_bfloat162 h0 = __floats2bfloat162_rn(dx * rstd * wv.x + bv.x, dy * rstd * wv.y + bv.y);
    __nv_bfloat162 h1 = __floats2bfloat162_rn(dz * rstd * wv.z + bv.z, dw * rstd * wv.w + bv.w);
    uint2 u; u.x = *(uint32_t*)&h0; u.y = *(uint32_t*)&h1;
    *(uint2*)(y + (size_t)t * D_MODEL + tid * 4) = u;
}

// ------------------------- bf16 tensor-core GEMM: C = A * W^T (+bias)(+resid) -------
// A: [M,K] bf16 row-major, W: [N,K] bf16 row-major. 128x128x64 tiles, double buffer.
#define TBM 128
#define TBN 128
#define GSTG 18432                         // bytes, one matrix one stage (128*144)
#define GEMM_SMEM (4 * GSTG)               // A0 W0 A1 W1

// rope_mode: 0 = none, 1 = rope (k), 2 = rope + 0.125 scale (q)
struct GemmOut {
    void* C;
    const float* bias;
    const float* resid;
    const float2* rope;
    int bf16_out;
    int rope_mode;
};

__device__ __forceinline__ void gemm_body(const __nv_bfloat16* __restrict__ A,
                                          const __nv_bfloat16* __restrict__ W,
                                          const GemmOut& out,
                                          int m0, int n0, char* smem) {
    const uint32_t sb = smem_u32(smem);
    const int tid  = threadIdx.x;
    const int wid  = tid >> 5, lane = tid & 31;
    const int wm   = wid >> 2, wn   = wid & 3;     // 2 x 4 warps, warp tile 64x32
    const int g    = lane >> 2, t   = lane & 3;

    float acc[4][4][4];
    #pragma unroll
    for (int a = 0; a < 4; ++a)
        #pragma unroll
        for (int b = 0; b < 4; ++b)
            #pragma unroll
            for (int c = 0; c < 4; ++c) acc[a][b][c] = 0.f;

    const uint32_t a_row = (uint32_t)(lane & 15);
    const uint32_t a_cb  = (uint32_t)((lane >> 4) << 4);
    const uint32_t b_row = (uint32_t)((lane & 7) + ((lane >> 4) << 3));
    const uint32_t b_cb  = (uint32_t)(((lane >> 3) & 1) << 4);

    #define GF(s_, kt_) do {                                                        \
        const int kk_ = (kt_) * 64;                                                 \
        _Pragma("unroll")                                                           \
        for (int c_ = 0; c_ < 4; ++c_) {                                            \
            const int j_ = tid + (c_ << 8);                                         \
            const int r_ = j_ >> 3, cc_ = j_ & 7;                                   \
            cp16(sb + (s_) * 2 * GSTG + r_ * 144 + cc_ * 16,                        \
                 A + (size_t)(m0 + r_) * D_MODEL + kk_ + cc_ * 8);                  \
            cp16(sb + (s_) * 2 * GSTG + GSTG + r_ * 144 + cc_ * 16,                 \
                 W + (size_t)(n0 + r_) * D_MODEL + kk_ + cc_ * 8);                  \
        }                                                                           \
    } while (0)

    GF(0, 0);
    CP_COMMIT;

    int cur = 0;
    #pragma unroll 1
    for (int tt = 0; tt < D_MODEL / 64; ++tt) {
        CP_WAIT_ALL;
        __syncthreads();
        if (tt + 1 < D_MODEL / 64) {
            GF(cur ^ 1, tt + 1);
            CP_COMMIT;
        }
        const uint32_t ab = sb + cur * 2 * GSTG;
        const uint32_t wb = ab + GSTG;
        #pragma unroll
        for (int s16 = 0; s16 < 4; ++s16) {
            const uint32_t kb = s16 * 32;
            uint32_t af[4][4], bf[4][4];
            #pragma unroll
            for (int mf = 0; mf < 4; ++mf)
                ldm4(af[mf], ab + (wm * 64 + mf * 16 + a_row) * 144 + a_cb + kb);
            #pragma unroll
            for (int nfp = 0; nfp < 2; ++nfp)
                ldm4(bf[nfp * 2], wb + (wn * 32 + nfp * 16 + b_row) * 144 + b_cb + kb);
            #pragma unroll
            for (int mf = 0; mf < 4; ++mf) {
                mma_bf16(acc[mf][0], af[mf], &bf[0][0]);
                mma_bf16(acc[mf][1], af[mf], &bf[0][2]);
                mma_bf16(acc[mf][2], af[mf], &bf[2][0]);
                mma_bf16(acc[mf][3], af[mf], &bf[2][2]);
            }
        }
        cur ^= 1;
    }
    #undef GF

    #pragma unroll
    for (int mf = 0; mf < 4; ++mf) {
        #pragma unroll
        for (int nf = 0; nf < 4; ++nf) {
            const int n = n0 + wn * 32 + nf * 8 + 2 * t;
            const float2 bz = *(const float2*)(out.bias + n);
            #pragma unroll
            for (int h = 0; h < 2; ++h) {
                const int m = m0 + wm * 64 + mf * 16 + g + 8 * h;
                float2 r2;
                r2.x = acc[mf][nf][2 * h + 0] + bz.x;
                r2.y = acc[mf][nf][2 * h + 1] + bz.y;
                if (out.rope_mode) {
                    const int pos = m & (SEQ - 1);
                    const int j   = (n & 63) >> 1;
                    const float2 cs = out.rope[pos * 32 + j];
                    const float x0 = r2.x, x1 = r2.y;
                    r2.x = x0 * cs.x - x1 * cs.y;
                    r2.y = x0 * cs.y + x1 * cs.x;
                    if (out.rope_mode == 2) { r2.x *= 0.125f; r2.y *= 0.125f; }
                }
                if (out.resid) {
                    const float2 rv = *(const float2*)(out.resid + (size_t)m * D_MODEL + n);
                    r2.x += rv.x; r2.y += rv.y;
                }
                if (out.bf16_out) {
                    __nv_bfloat162 hh = __floats2bfloat162_rn(r2.x, r2.y);
                    *(__nv_bfloat162*)((__nv_bfloat16*)out.C + (size_t)m * D_MODEL + n) = hh;
                } else {
                    *(float2*)((float*)out.C + (size_t)m * D_MODEL + n) = r2;
                }
            }
        }
    }
}

// fused QKV: grid.x in [0,24): tiles 0-7 -> q (rope+scale), 8-15 -> k (rope), 16-23 -> v
__global__ __launch_bounds__(256, 2) void gemm_qkv(const __nv_bfloat16* __restrict__ xn,
                                                   const __nv_bfloat16* __restrict__ wbuf,
                                                   const float* __restrict__ bq,
                                                   const float* __restrict__ bk,
                                                   const float* __restrict__ bv,
                                                   __nv_bfloat16* __restrict__ q,
                                                   __nv_bfloat16* __restrict__ k,
                                                   __nv_bfloat16* __restrict__ v,
                                                   const float2* __restrict__ rope) {
    extern __shared__ char smc[];
    const int which = blockIdx.x >> 3;
    const int n0    = (blockIdx.x & 7) * TBN;
    const int m0    = blockIdx.y * TBM;
    GemmOut o;
    if (which == 0)      { o.C = q; o.bias = bq; o.rope_mode = 2; }
    else if (which == 1) { o.C = k; o.bias = bk; o.rope_mode = 1; }
    else                 { o.C = v; o.bias = bv; o.rope_mode = 0; }
    o.resid = nullptr; o.bf16_out = 1; o.rope = rope;
    gemm_body(xn, wbuf + (size_t)which * D_MODEL * D_MODEL, o, m0, n0, smc);
}

__global__ __launch_bounds__(256, 2) void gemm_oproj(const __nv_bfloat16* __restrict__ att,
                                                     const __nv_bfloat16* __restrict__ Wo,
                                                     const float* __restrict__ bo,
                                                     const float* __restrict__ x,
                                                     float* __restrict__ out) {
    extern __shared__ char smc[];
    GemmOut o; o.C = out; o.bias = bo; o.resid = x; o.bf16_out = 0;
    o.rope = nullptr; o.rope_mode = 0;
    gemm_body(att, Wo, o, blockIdx.y * TBM, blockIdx.x * TBN, smc);
}

// ------------------------ flash attention, bf16 tensor cores ------------------------
// q-tile 128, k-tile 64, hd 64. 8 warps x 16 q-rows. 2-stage K/V cp.async pipeline.
// q is pre-scaled by 1/sqrt(hd); rope already applied.
#define AQ  128
#define AKT 64
#define NT  (SEQ / AKT)  // 32
#define QS_B (128 * 144)
#define KV_B (64 * 144)
// layout: Q | K0 V0 | K1 V1 | P
#define ATT_SMEM (QS_B + 4 * KV_B + 128 * 144)   // 73728

__global__ __launch_bounds__(256, 2) void attn_tc(const __nv_bfloat16* __restrict__ qg,
                                                  const __nv_bfloat16* __restrict__ kg,
                                                  const __nv_bfloat16* __restrict__ vg,
                                                  __nv_bfloat16* __restrict__ og) {
    extern __shared__ char smc[];
    const uint32_t sb   = smem_u32(smc);
    const uint32_t qoff = sb;
    const uint32_t poff = sb + QS_B + 4 * KV_B;
    __nv_bfloat16* Psp = (__nv_bfloat16*)(smc + QS_B + 4 * KV_B);

    const int tid  = threadIdx.x, wid = tid >> 5, lane = tid & 31;
    const int g    = lane >> 2, t = lane & 3;
    const int q0   = blockIdx.x * AQ;
    const size_t cbase = (size_t)blockIdx.z * SEQ * D_MODEL + (size_t)blockIdx.y * HEAD_DIM;
    const int wrow = wid * 16;

    const uint32_t a_row = (uint32_t)(lane & 15);
    const uint32_t a_cb  = (uint32_t)((lane >> 4) << 4);
    const uint32_t b_row = (uint32_t)((lane & 7) + ((lane >> 4) << 3));
    const uint32_t b_cb  = (uint32_t)(((lane >> 3) & 1) << 4);

    // issue K,V copy of tile tt_ into stage s_
    #define AKV(s_, tt_) do {                                                       \
        const uint32_t kb_ = sb + QS_B + (s_) * 2 * KV_B;                           \
        _Pragma("unroll")                                                           \
        for (int c_ = 0; c_ < 2; ++c_) {                                            \
            const int j_ = tid + (c_ << 8);                                         \
            const int r_ = j_ >> 3, cc_ = j_ & 7;                                   \
            const size_t go_ = cbase + (size_t)((tt_) * AKT + r_) * D_MODEL + cc_ * 8; \
            cp16(kb_ + r_ * 144 + cc_ * 16, kg + go_);                              \
            cp16(kb_ + KV_B + r_ * 144 + cc_ * 16, vg + go_);                       \
        }                                                                           \
    } while (0)

    // prologue: Q + stage0 (group A), stage1 (group B)
    #pragma unroll
    for (int c = 0; c < 4; ++c) {
        const int j = tid + (c << 8);
        const int r = j >> 3, cc = j & 7;
        cp16(qoff + r * 144 + cc * 16, qg + cbase + (size_t)(q0 + r) * D_MODEL + cc * 8);
    }
    AKV(0, 0);
    CP_COMMIT;
    AKV(1, 1);
    CP_COMMIT;

    float oacc[8][4];
    float mst[2] = { -1e30f, -1e30f }, lst[2] = { 0.f, 0.f };
    #pragma unroll
    for (int df = 0; df < 8; ++df)
        #pragma unroll
        for (int c = 0; c < 4; ++c) oacc[df][c] = 0.f;

    #pragma unroll 1
    for (int kt = 0; kt < NT; ++kt) {
        const int s = kt & 1;
        const uint32_t koff = sb + QS_B + s * 2 * KV_B;
        const uint32_t voff = koff + KV_B;

        CP_WAIT_GROUP(1);
        __syncthreads();

        // ---- S = Q K^T (q pre-scaled) ----
        float sacc[8][4];
        #pragma unroll
        for (int nf = 0; nf < 8; ++nf)
            #pragma unroll
            for (int c = 0; c < 4; ++c) sacc[nf][c] = 0.f;

        #pragma unroll
        for (int s16 = 0; s16 < 4; ++s16) {
            const uint32_t kb = s16 * 32;
            uint32_t af[4];
            ldm4(af, qoff + (wrow + a_row) * 144 + a_cb + kb);
            #pragma unroll
            for (int nfp = 0; nfp < 4; ++nfp) {
                uint32_t t4[4];
                ldm4(t4, koff + (nfp * 16 + b_row) * 144 + b_cb + kb);
                mma_bf16(sacc[nfp * 2],     af, &t4[0]);
                mma_bf16(sacc[nfp * 2 + 1], af, &t4[2]);
            }
        }

        // ---- online softmax (rows g, g+8; reduce over 4 lanes of thread-row) ----
        #pragma unroll
        for (int h = 0; h < 2; ++h) {
            float rm = -1e30f;
            #pragma unroll
            for (int nf = 0; nf < 8; ++nf)
                rm = fmaxf(rm, fmaxf(sacc[nf][2 * h], sacc[nf][2 * h + 1]));
            rm = fmaxf(rm, __shfl_xor_sync(0xffffffffu, rm, 1));
            rm = fmaxf(rm, __shfl_xor_sync(0xffffffffu, rm, 2));
            const float mnew = fmaxf(mst[h], rm);
            const float corr = __expf(mst[h] - mnew);
            float ps = 0.f;
            const int prow = wrow + g + 8 * h;
            #pragma unroll
            for (int nf = 0; nf < 8; ++nf) {
                const float p0 = __expf(sacc[nf][2 * h]     - mnew);
                const float p1 = __expf(sacc[nf][2 * h + 1] - mnew);
                ps += p0 + p1;
                *(__nv_bfloat162*)&Psp[prow * 72 + nf * 8 + 2 * t] = __floats2bfloat162_rn(p0, p1);
            }
            ps += __shfl_xor_sync(0xffffffffu, ps, 1);
            ps += __shfl_xor_sync(0xffffffffu, ps, 2);
            lst[h] = lst[h] * corr + ps;
            mst[h] = mnew;
            #pragma unroll
            for (int df = 0; df < 8; ++df) {
                oacc[df][2 * h]     *= corr;
                oacc[df][2 * h + 1] *= corr;
            }
        }
        __syncwarp();   // P is warp-local (each warp owns its 16 rows)

        // ---- O += P V ----
        #pragma unroll
        for (int s16 = 0; s16 < 4; ++s16) {
            const uint32_t kb = s16 * 32;
            uint32_t af[4];
            ldm4(af, poff + (wrow + a_row) * 144 + a_cb + kb);
            #pragma unroll
            for (int nfp = 0; nfp < 4; ++nfp) {
                uint32_t t4[4];
                ldm4t(t4, voff + (s16 * 16 + a_row) * 144 + a_cb + nfp * 32);
                mma_bf16(oacc[nfp * 2],     af, &t4[0]);
                mma_bf16(oacc[nfp * 2 + 1], af, &t4[2]);
            }
        }

        __syncthreads();   // all warps done reading K[s], V[s]
        if (kt + 2 < NT) AKV(s, kt + 2);
        CP_COMMIT;         // one group per iter (possibly empty) keeps counts aligned
    }
    #undef AKV

    // ---- finalize: /l, bf16 out (feeds o-proj GEMM) ----
    #pragma unroll
    for (int h = 0; h < 2; ++h) {
        const float inv = 1.f / lst[h];
        const int row = q0 + wrow + g + 8 * h;
        #pragma unroll
        for (int df = 0; df < 8; ++df) {
            __nv_bfloat162 o2 = __floats2bfloat162_rn(oacc[df][2 * h] * inv,
                                                      oacc[df][2 * h + 1] * inv);
            *(__nv_bfloat162*)(og + cbase + (size_t)row * D_MODEL + df * 8 + 2 * t) = o2;
        }
    }
}

// ---------------------------------- launch ------------------------------------------
extern "C" void kernel_launch(void* const* d_in, const int* in_sizes, int n_in,
                              void* d_out, int out_size) {
    const float* x    = (const float*)d_in[0];
    const float* ln_w = (const float*)d_in[1];
    const float* ln_b = (const float*)d_in[2];
    const float* Wq   = (const float*)d_in[3];
    const float* bq   = (const float*)d_in[4];
    const float* Wk   = (const float*)d_in[5];
    const float* bk   = (const float*)d_in[6];
    const float* Wv   = (const float*)d_in[7];
    const float* bv   = (const float*)d_in[8];
    const float* Wo   = (const float*)d_in[9];
    const float* bo   = (const float*)d_in[10];
    float* out = (float*)d_out;

    __nv_bfloat16 *xn, *q, *k, *v, *att, *wbuf;
    float2* rope;
    cudaGetSymbolAddress((void**)&xn,  g_xn);
    cudaGetSymbolAddress((void**)&q,   g_q);
    cudaGetSymbolAddress((void**)&k,   g_k);
    cudaGetSymbolAddress((void**)&v,   g_v);
    cudaGetSymbolAddress((void**)&att, g_att);
    cudaGetSymbolAddress((void**)&wbuf, g_w);
    cudaGetSymbolAddress((void**)&rope, g_rope);
    const size_t WN = (size_t)D_MODEL * D_MODEL;

    rope_table_kernel<<<SEQ * 32 / 256, 256>>>(rope);
    round_w_kernel<<<(int)(WN / 4 / 256), 256>>>(Wq, Wk, Wv, Wo, wbuf);
    ln_kernel<<<NTOK, 256>>>(x, ln_w, ln_b, xn);

    cudaFuncSetAttribute(gemm_qkv,   cudaFuncAttributeMaxDynamicSharedMemorySize, GEMM_SMEM);
    cudaFuncSetAttribute(gemm_oproj, cudaFuncAttributeMaxDynamicSharedMemorySize, GEMM_SMEM);

    gemm_qkv<<<dim3(24, NTOK / TBM), 256, GEMM_SMEM>>>(xn, wbuf, bq, bk, bv, q, k, v, rope);

    cudaFuncSetAttribute(attn_tc, cudaFuncAttributeMaxDynamicSharedMemorySize, ATT_SMEM);
    attn_tc<<<dim3(SEQ / AQ, NHEAD, BATCH), 256, ATT_SMEM>>>(q, k, v, att);

    gemm_oproj<<<dim3(D_MODEL / TBN, NTOK / TBM), 256, GEMM_SMEM>>>(att, wbuf + 3 * WN, bo, x, out);
}

// round 7
// speedup vs baseline: 6.0746x; 1.0069x over previous
#include <cuda_runtime.h>
#include <cuda_bf16.h>
#include <math.h>
#include <stdint.h>

#define D_MODEL 1024
#define NHEAD   16
#define HEAD_DIM 64
#define BATCH   2
#define SEQ     2048
#define NTOK    (BATCH * SEQ)   // 4096

// ------------------------- scratch (no allocations allowed) -------------------------
__device__ __nv_bfloat16 g_xn [NTOK * D_MODEL];
__device__ __nv_bfloat16 g_q  [NTOK * D_MODEL];
__device__ __nv_bfloat16 g_k  [NTOK * D_MODEL];
__device__ __nv_bfloat16 g_v  [NTOK * D_MODEL];
__device__ __nv_bfloat16 g_att[NTOK * D_MODEL];
__device__ __nv_bfloat16 g_w  [4 * D_MODEL * D_MODEL];   // bf16 Wq,Wk,Wv,Wo
__device__ float2        g_rope[SEQ * 32];               // cos/sin table

// ------------------------------- helpers --------------------------------------------
__device__ __forceinline__ void mma_bf16(float* d, const uint32_t* a, const uint32_t* b) {
    asm volatile(
        "mma.sync.aligned.m16n8k16.row.col.f32.bf16.bf16.f32 "
        "{%0,%1,%2,%3}, {%4,%5,%6,%7}, {%8,%9}, {%0,%1,%2,%3};"
        : "+f"(d[0]), "+f"(d[1]), "+f"(d[2]), "+f"(d[3])
        : "r"(a[0]), "r"(a[1]), "r"(a[2]), "r"(a[3]), "r"(b[0]), "r"(b[1]));
}
__device__ __forceinline__ void ldm4(uint32_t* r, uint32_t a) {
    asm volatile("ldmatrix.sync.aligned.m8n8.x4.shared.b16 {%0,%1,%2,%3}, [%4];"
        : "=r"(r[0]), "=r"(r[1]), "=r"(r[2]), "=r"(r[3]) : "r"(a));
}
__device__ __forceinline__ void ldm4t(uint32_t* r, uint32_t a) {
    asm volatile("ldmatrix.sync.aligned.m8n8.x4.trans.shared.b16 {%0,%1,%2,%3}, [%4];"
        : "=r"(r[0]), "=r"(r[1]), "=r"(r[2]), "=r"(r[3]) : "r"(a));
}
__device__ __forceinline__ uint32_t smem_u32(const void* p) {
    return (uint32_t)__cvta_generic_to_shared(p);
}
__device__ __forceinline__ void cp16(uint32_t s, const void* g) {
    asm volatile("cp.async.cg.shared.global [%0], [%1], 16;" :: "r"(s), "l"(g));
}
#define CP_COMMIT   asm volatile("cp.async.commit_group;")
#define CP_WAIT_GROUP(n) asm volatile("cp.async.wait_group %0;" :: "n"(n))

// ------------------------------- rope table -----------------------------------------
__global__ __launch_bounds__(256) void rope_table_kernel(float2* __restrict__ tab) {
    const int idx = blockIdx.x * 256 + threadIdx.x;   // < SEQ*32
    const int pos = idx >> 5, j = idx & 31;
    const float inv = expf(-(float)(2 * j) * (9.210340371976184f / 64.f));
    float sn, cs;
    sincosf((float)pos * inv, &sn, &cs);
    tab[idx] = make_float2(cs, sn);
}

// ------------------------------- weight pre-round to bf16 ---------------------------
__global__ __launch_bounds__(256) void round_w_kernel(const float* __restrict__ a,
                                                      const float* __restrict__ b,
                                                      const float* __restrict__ c,
                                                      const float* __restrict__ d,
                                                      __nv_bfloat16* __restrict__ o) {
    const int i = blockIdx.x * 256 + threadIdx.x;          // float4 index
    const int n4 = D_MODEL * D_MODEL / 4;
    const float4 va = reinterpret_cast<const float4*>(a)[i];
    const float4 vb = reinterpret_cast<const float4*>(b)[i];
    const float4 vc = reinterpret_cast<const float4*>(c)[i];
    const float4 vd = reinterpret_cast<const float4*>(d)[i];
    uint2 u;
    __nv_bfloat162 h0, h1;
    h0 = __floats2bfloat162_rn(va.x, va.y); h1 = __floats2bfloat162_rn(va.z, va.w);
    u.x = *(uint32_t*)&h0; u.y = *(uint32_t*)&h1;
    *(uint2*)(o + (size_t)i * 4) = u;
    h0 = __floats2bfloat162_rn(vb.x, vb.y); h1 = __floats2bfloat162_rn(vb.z, vb.w);
    u.x = *(uint32_t*)&h0; u.y = *(uint32_t*)&h1;
    *(uint2*)(o + (size_t)(n4 + i) * 4) = u;
    h0 = __floats2bfloat162_rn(vc.x, vc.y); h1 = __floats2bfloat162_rn(vc.z, vc.w);
    u.x = *(uint32_t*)&h0; u.y = *(uint32_t*)&h1;
    *(uint2*)(o + (size_t)(2 * n4 + i) * 4) = u;
    h0 = __floats2bfloat162_rn(vd.x, vd.y); h1 = __floats2bfloat162_rn(vd.z, vd.w);
    u.x = *(uint32_t*)&h0; u.y = *(uint32_t*)&h1;
    *(uint2*)(o + (size_t)(3 * n4 + i) * 4) = u;
}

// ------------------------------- LayerNorm (bf16 out) -------------------------------
__global__ __launch_bounds__(256) void ln_kernel(const float* __restrict__ x,
                                                 const float* __restrict__ w,
                                                 const float* __restrict__ b,
                                                 __nv_bfloat16* __restrict__ y) {
    const int t   = blockIdx.x;
    const int tid = threadIdx.x;
    const float4* xr = reinterpret_cast<const float4*>(x + (size_t)t * D_MODEL);
    float4 v = xr[tid];

    __shared__ float red[8];
    float s = v.x + v.y + v.z + v.w;
    #pragma unroll
    for (int m = 16; m >= 1; m >>= 1) s += __shfl_xor_sync(0xffffffffu, s, m);
    if ((tid & 31) == 0) red[tid >> 5] = s;
    __syncthreads();
    float tot = 0.f;
    #pragma unroll
    for (int i = 0; i < 8; ++i) tot += red[i];
    const float mu = tot * (1.0f / D_MODEL);
    __syncthreads();

    const float dx = v.x - mu, dy = v.y - mu, dz = v.z - mu, dw = v.w - mu;
    float sq = dx*dx + dy*dy + dz*dz + dw*dw;
    #pragma unroll
    for (int m = 16; m >= 1; m >>= 1) sq += __shfl_xor_sync(0xffffffffu, sq, m);
    if ((tid & 31) == 0) red[tid >> 5] = sq;
    __syncthreads();
    float tot2 = 0.f;
    #pragma unroll
    for (int i = 0; i < 8; ++i) tot2 += red[i];
    const float rstd = rsqrtf(tot2 * (1.0f / D_MODEL) + 1e-5f);

    const float4 wv = reinterpret_cast<const float4*>(w)[tid];
    const float4 bv = reinterpret_cast<const float4*>(b)[tid];
    __nv_bfloat162 h0 = __floats2bfloat162_rn(dx * rstd * wv.x + bv.x, dy * rstd * wv.y + bv.y);
    __nv_bfloat162 h1 = __floats2bfloat162_rn(dz * rstd * wv.z + bv.z, dw * rstd * wv.w + bv.w);
    uint2 u; u.x = *(uint32_t*)&h0; u.y = *(uint32_t*)&h1;
    *(uint2*)(y + (size_t)t * D_MODEL + tid * 4) = u;
}

// ------------------------- bf16 tensor-core GEMM: C = A * W^T (+bias)(+resid) -------
// A: [M,K] bf16 row-major, W: [N,K] bf16 row-major. 128x128x64 tiles.
// 3-stage cp.async pipeline: the wait targets a copy issued TWO iterations back.
#define TBM 128
#define TBN 128
#define GSTG 18432                         // bytes, one matrix one stage (128*144)
#define STAGE_B (2 * GSTG)                 // A + W per stage
#define GEMM_SMEM (3 * STAGE_B)            // 110592

// rope_mode: 0 = none, 1 = rope (k), 2 = rope + 0.125 scale (q)
struct GemmOut {
    void* C;
    const float* bias;
    const float* resid;
    const float2* rope;
    int bf16_out;
    int rope_mode;
};

__device__ __forceinline__ void gemm_body(const __nv_bfloat16* __restrict__ A,
                                          const __nv_bfloat16* __restrict__ W,
                                          const GemmOut& out,
                                          int m0, int n0, char* smem) {
    const uint32_t sb = smem_u32(smem);
    const int tid  = threadIdx.x;
    const int wid  = tid >> 5, lane = tid & 31;
    const int wm   = wid >> 2, wn   = wid & 3;     // 2 x 4 warps, warp tile 64x32
    const int g    = lane >> 2, t   = lane & 3;

    float acc[4][4][4];
    #pragma unroll
    for (int a = 0; a < 4; ++a)
        #pragma unroll
        for (int b = 0; b < 4; ++b)
            #pragma unroll
            for (int c = 0; c < 4; ++c) acc[a][b][c] = 0.f;

    const uint32_t a_row = (uint32_t)(lane & 15);
    const uint32_t a_cb  = (uint32_t)((lane >> 4) << 4);
    const uint32_t b_row = (uint32_t)((lane & 7) + ((lane >> 4) << 3));
    const uint32_t b_cb  = (uint32_t)(((lane >> 3) & 1) << 4);

    #define GF(s_, kt_) do {                                                        \
        const int kk_ = (kt_) * 64;                                                 \
        _Pragma("unroll")                                                           \
        for (int c_ = 0; c_ < 4; ++c_) {                                            \
            const int j_ = tid + (c_ << 8);                                         \
            const int r_ = j_ >> 3, cc_ = j_ & 7;                                   \
            cp16(sb + (s_) * STAGE_B + r_ * 144 + cc_ * 16,                         \
                 A + (size_t)(m0 + r_) * D_MODEL + kk_ + cc_ * 8);                  \
            cp16(sb + (s_) * STAGE_B + GSTG + r_ * 144 + cc_ * 16,                  \
                 W + (size_t)(n0 + r_) * D_MODEL + kk_ + cc_ * 8);                  \
        }                                                                           \
    } while (0)

    GF(0, 0);
    CP_COMMIT;
    GF(1, 1);
    CP_COMMIT;

    int s = 0, sf = 2;
    #pragma unroll 1
    for (int tt = 0; tt < D_MODEL / 64; ++tt) {
        CP_WAIT_GROUP(1);      // stage s ready (copy issued 2 iters ago)
        __syncthreads();       // also: all warps done with stage sf's previous contents
        if (tt + 2 < D_MODEL / 64) GF(sf, tt + 2);
        CP_COMMIT;             // exactly one group per iteration
        const uint32_t ab = sb + s * STAGE_B;
        const uint32_t wb = ab + GSTG;
        #pragma unroll
        for (int s16 = 0; s16 < 4; ++s16) {
            const uint32_t kb = s16 * 32;
            uint32_t af[4][4], bf[4][4];
            #pragma unroll
            for (int mf = 0; mf < 4; ++mf)
                ldm4(af[mf], ab + (wm * 64 + mf * 16 + a_row) * 144 + a_cb + kb);
            #pragma unroll
            for (int nfp = 0; nfp < 2; ++nfp)
                ldm4(bf[nfp * 2], wb + (wn * 32 + nfp * 16 + b_row) * 144 + b_cb + kb);
            #pragma unroll
            for (int mf = 0; mf < 4; ++mf) {
                mma_bf16(acc[mf][0], af[mf], &bf[0][0]);
                mma_bf16(acc[mf][1], af[mf], &bf[0][2]);
                mma_bf16(acc[mf][2], af[mf], &bf[2][0]);
                mma_bf16(acc[mf][3], af[mf], &bf[2][2]);
            }
        }
        if (++s == 3) s = 0;
        if (++sf == 3) sf = 0;
    }
    #undef GF

    #pragma unroll
    for (int mf = 0; mf < 4; ++mf) {
        #pragma unroll
        for (int nf = 0; nf < 4; ++nf) {
            const int n = n0 + wn * 32 + nf * 8 + 2 * t;
            const float2 bz = *(const float2*)(out.bias + n);
            #pragma unroll
            for (int h = 0; h < 2; ++h) {
                const int m = m0 + wm * 64 + mf * 16 + g + 8 * h;
                float2 r2;
                r2.x = acc[mf][nf][2 * h + 0] + bz.x;
                r2.y = acc[mf][nf][2 * h + 1] + bz.y;
                if (out.rope_mode) {
                    const int pos = m & (SEQ - 1);
                    const int j   = (n & 63) >> 1;
                    const float2 cs = out.rope[pos * 32 + j];
                    const float x0 = r2.x, x1 = r2.y;
                    r2.x = x0 * cs.x - x1 * cs.y;
                    r2.y = x0 * cs.y + x1 * cs.x;
                    if (out.rope_mode == 2) { r2.x *= 0.125f; r2.y *= 0.125f; }
                }
                if (out.resid) {
                    const float2 rv = *(const float2*)(out.resid + (size_t)m * D_MODEL + n);
                    r2.x += rv.x; r2.y += rv.y;
                }
                if (out.bf16_out) {
                    __nv_bfloat162 hh = __floats2bfloat162_rn(r2.x, r2.y);
                    *(__nv_bfloat162*)((__nv_bfloat16*)out.C + (size_t)m * D_MODEL + n) = hh;
                } else {
                    *(float2*)((float*)out.C + (size_t)m * D_MODEL + n) = r2;
                }
            }
        }
    }
}

// fused QKV: grid.x in [0,24): tiles 0-7 -> q (rope+scale), 8-15 -> k (rope), 16-23 -> v
__global__ __launch_bounds__(256, 2) void gemm_qkv(const __nv_bfloat16* __restrict__ xn,
                                                   const __nv_bfloat16* __restrict__ wbuf,
                                                   const float* __restrict__ bq,
                                                   const float* __restrict__ bk,
                                                   const float* __restrict__ bv,
                                                   __nv_bfloat16* __restrict__ q,
                                                   __nv_bfloat16* __restrict__ k,
                                                   __nv_bfloat16* __restrict__ v,
                                                   const float2* __restrict__ rope) {
    extern __shared__ char smc[];
    const int which = blockIdx.x >> 3;
    const int n0    = (blockIdx.x & 7) * TBN;
    const int m0    = blockIdx.y * TBM;
    GemmOut o;
    if (which == 0)      { o.C = q; o.bias = bq; o.rope_mode = 2; }
    else if (which == 1) { o.C = k; o.bias = bk; o.rope_mode = 1; }
    else                 { o.C = v; o.bias = bv; o.rope_mode = 0; }
    o.resid = nullptr; o.bf16_out = 1; o.rope = rope;
    gemm_body(xn, wbuf + (size_t)which * D_MODEL * D_MODEL, o, m0, n0, smc);
}

__global__ __launch_bounds__(256, 2) void gemm_oproj(const __nv_bfloat16* __restrict__ att,
                                                     const __nv_bfloat16* __restrict__ Wo,
                                                     const float* __restrict__ bo,
                                                     const float* __restrict__ x,
                                                     float* __restrict__ out) {
    extern __shared__ char smc[];
    GemmOut o; o.C = out; o.bias = bo; o.resid = x; o.bf16_out = 0;
    o.rope = nullptr; o.rope_mode = 0;
    gemm_body(att, Wo, o, blockIdx.y * TBM, blockIdx.x * TBN, smc);
}

// ------------------------ flash attention, bf16 tensor cores ------------------------
// q-tile 128, k-tile 64, hd 64. 8 warps x 16 q-rows. 3-stage K/V cp.async ring.
// q is pre-scaled by 1/sqrt(hd); rope already applied.
#define AQ  128
#define AKT 64
#define NT  (SEQ / AKT)  // 32
#define QS_B (128 * 144)
#define KV_B (64 * 144)
// layout: Q | K0 V0 | K1 V1 | K2 V2 | P
#define ATT_SMEM (QS_B + 6 * KV_B + 128 * 144)   // 92160

__global__ __launch_bounds__(256, 2) void attn_tc(const __nv_bfloat16* __restrict__ qg,
                                                  const __nv_bfloat16* __restrict__ kg,
                                                  const __nv_bfloat16* __restrict__ vg,
                                                  __nv_bfloat16* __restrict__ og) {
    extern __shared__ char smc[];
    const uint32_t sb   = smem_u32(smc);
    const uint32_t qoff = sb;
    const uint32_t poff = sb + QS_B + 6 * KV_B;
    __nv_bfloat16* Psp = (__nv_bfloat16*)(smc + QS_B + 6 * KV_B);

    const int tid  = threadIdx.x, wid = tid >> 5, lane = tid & 31;
    const int g    = lane >> 2, t = lane & 3;
    const int q0   = blockIdx.x * AQ;
    const size_t cbase = (size_t)blockIdx.z * SEQ * D_MODEL + (size_t)blockIdx.y * HEAD_DIM;
    const int wrow = wid * 16;

    const uint32_t a_row = (uint32_t)(lane & 15);
    const uint32_t a_cb  = (uint32_t)((lane >> 4) << 4);
    const uint32_t b_row = (uint32_t)((lane & 7) + ((lane >> 4) << 3));
    const uint32_t b_cb  = (uint32_t)(((lane >> 3) & 1) << 4);

    #define AKV(s_, tt_) do {                                                       \
        const uint32_t kb_ = sb + QS_B + (s_) * 2 * KV_B;                           \
        _Pragma("unroll")                                                           \
        for (int c_ = 0; c_ < 2; ++c_) {                                            \
            const int j_ = tid + (c_ << 8);                                         \
            const int r_ = j_ >> 3, cc_ = j_ & 7;                                   \
            const size_t go_ = cbase + (size_t)((tt_) * AKT + r_) * D_MODEL + cc_ * 8; \
            cp16(kb_ + r_ * 144 + cc_ * 16, kg + go_);                              \
            cp16(kb_ + KV_B + r_ * 144 + cc_ * 16, vg + go_);                       \
        }                                                                           \
    } while (0)

    // prologue: Q + stage0 (group0), stage1 (group1)
    #pragma unroll
    for (int c = 0; c < 4; ++c) {
        const int j = tid + (c << 8);
        const int r = j >> 3, cc = j & 7;
        cp16(qoff + r * 144 + cc * 16, qg + cbase + (size_t)(q0 + r) * D_MODEL + cc * 8);
    }
    AKV(0, 0);
    CP_COMMIT;
    AKV(1, 1);
    CP_COMMIT;

    float oacc[8][4];
    float mst[2] = { -1e30f, -1e30f }, lst[2] = { 0.f, 0.f };
    #pragma unroll
    for (int df = 0; df < 8; ++df)
        #pragma unroll
        for (int c = 0; c < 4; ++c) oacc[df][c] = 0.f;

    int s = 0, sf = 2;
    #pragma unroll 1
    for (int kt = 0; kt < NT; ++kt) {
        const uint32_t koff = sb + QS_B + s * 2 * KV_B;
        const uint32_t voff = koff + KV_B;

        CP_WAIT_GROUP(1);      // stage s ready (issued 2 iters ago)
        __syncthreads();       // all warps done with stage sf's old contents
        if (kt + 2 < NT) AKV(sf, kt + 2);
        CP_COMMIT;

        // ---- S = Q K^T (q pre-scaled) ----
        float sacc[8][4];
        #pragma unroll
        for (int nf = 0; nf < 8; ++nf)
            #pragma unroll
            for (int c = 0; c < 4; ++c) sacc[nf][c] = 0.f;

        #pragma unroll
        for (int s16 = 0; s16 < 4; ++s16) {
            const uint32_t kb = s16 * 32;
            uint32_t af[4];
            ldm4(af, qoff + (wrow + a_row) * 144 + a_cb + kb);
            #pragma unroll
            for (int nfp = 0; nfp < 4; ++nfp) {
                uint32_t t4[4];
                ldm4(t4, koff + (nfp * 16 + b_row) * 144 + b_cb + kb);
                mma_bf16(sacc[nfp * 2],     af, &t4[0]);
                mma_bf16(sacc[nfp * 2 + 1], af, &t4[2]);
            }
        }

        // ---- online softmax (rows g, g+8; reduce over 4 lanes of thread-row) ----
        #pragma unroll
        for (int h = 0; h < 2; ++h) {
            float rm = -1e30f;
            #pragma unroll
            for (int nf = 0; nf < 8; ++nf)
                rm = fmaxf(rm, fmaxf(sacc[nf][2 * h], sacc[nf][2 * h + 1]));
            rm = fmaxf(rm, __shfl_xor_sync(0xffffffffu, rm, 1));
            rm = fmaxf(rm, __shfl_xor_sync(0xffffffffu, rm, 2));
            const float mnew = fmaxf(mst[h], rm);
            const float corr = __expf(mst[h] - mnew);
            float ps = 0.f;
            const int prow = wrow + g + 8 * h;
            #pragma unroll
            for (int nf = 0; nf < 8; ++nf) {
                const float p0 = __expf(sacc[nf][2 * h]     - mnew);
                const float p1 = __expf(sacc[nf][2 * h + 1] - mnew);
                ps += p0 + p1;
                *(__nv_bfloat162*)&Psp[prow * 72 + nf * 8 + 2 * t] = __floats2bfloat162_rn(p0, p1);
            }
            ps += __shfl_xor_sync(0xffffffffu, ps, 1);
            ps += __shfl_xor_sync(0xffffffffu, ps, 2);
            lst[h] = lst[h] * corr + ps;
            mst[h] = mnew;
            #pragma unroll
            for (int df = 0; df < 8; ++df) {
                oacc[df][2 * h]     *= corr;
                oacc[df][2 * h + 1] *= corr;
            }
        }
        __syncwarp();   // P is warp-local (each warp owns its 16 rows)

        // ---- O += P V ----
        #pragma unroll
        for (int s16 = 0; s16 < 4; ++s16) {
            const uint32_t kb = s16 * 32;
            uint32_t af[4];
            ldm4(af, poff + (wrow + a_row) * 144 + a_cb + kb);
            #pragma unroll
            for (int nfp = 0; nfp < 4; ++nfp) {
                uint32_t t4[4];
                ldm4t(t4, voff + (s16 * 16 + a_row) * 144 + a_cb + nfp * 32);
                mma_bf16(oacc[nfp * 2],     af, &t4[0]);
                mma_bf16(oacc[nfp * 2 + 1], af, &t4[2]);
            }
        }

        if (++s == 3) s = 0;
        if (++sf == 3) sf = 0;
    }
    #undef AKV

    // ---- finalize: /l, bf16 out (feeds o-proj GEMM) ----
    #pragma unroll
    for (int h = 0; h < 2; ++h) {
        const float inv = 1.f / lst[h];
        const int row = q0 + wrow + g + 8 * h;
        #pragma unroll
        for (int df = 0; df < 8; ++df) {
            __nv_bfloat162 o2 = __floats2bfloat162_rn(oacc[df][2 * h] * inv,
                                                      oacc[df][2 * h + 1] * inv);
            *(__nv_bfloat162*)(og + cbase + (size_t)row * D_MODEL + df * 8 + 2 * t) = o2;
        }
    }
}

// ---------------------------------- launch ------------------------------------------
extern "C" void kernel_launch(void* const* d_in, const int* in_sizes, int n_in,
                              void* d_out, int out_size) {
    const float* x    = (const float*)d_in[0];
    const float* ln_w = (const float*)d_in[1];
    const float* ln_b = (const float*)d_in[2];
    const float* Wq   = (const float*)d_in[3];
    const float* bq   = (const float*)d_in[4];
    const float* Wk   = (const float*)d_in[5];
    const float* bk   = (const float*)d_in[6];
    const float* Wv   = (const float*)d_in[7];
    const float* bv   = (const float*)d_in[8];
    const float* Wo   = (const float*)d_in[9];
    const float* bo   = (const float*)d_in[10];
    float* out = (float*)d_out;

    __nv_bfloat16 *xn, *q, *k, *v, *att, *wbuf;
    float2* rope;
    cudaGetSymbolAddress((void**)&xn,  g_xn);
    cudaGetSymbolAddress((void**)&q,   g_q);
    cudaGetSymbolAddress((void**)&k,   g_k);
    cudaGetSymbolAddress((void**)&v,   g_v);
    cudaGetSymbolAddress((void**)&att, g_att);
    cudaGetSymbolAddress((void**)&wbuf, g_w);
    cudaGetSymbolAddress((void**)&rope, g_rope);
    const size_t WN = (size_t)D_MODEL * D_MODEL;

    rope_table_kernel<<<SEQ * 32 / 256, 256>>>(rope);
    round_w_kernel<<<(int)(WN / 4 / 256), 256>>>(Wq, Wk, Wv, Wo, wbuf);
    ln_kernel<<<NTOK, 256>>>(x, ln_w, ln_b, xn);

    cudaFuncSetAttribute(gemm_qkv,   cudaFuncAttributeMaxDynamicSharedMemorySize, GEMM_SMEM);
    cudaFuncSetAttribute(gemm_oproj, cudaFuncAttributeMaxDynamicSharedMemorySize, GEMM_SMEM);

    gemm_qkv<<<dim3(24, NTOK / TBM), 256, GEMM_SMEM>>>(xn, wbuf, bq, bk, bv, q, k, v, rope);

    cudaFuncSetAttribute(attn_tc, cudaFuncAttributeMaxDynamicSharedMemorySize, ATT_SMEM);
    attn_tc<<<dim3(SEQ / AQ, NHEAD, BATCH), 256, ATT_SMEM>>>(q, k, v, att);

    gemm_oproj<<<dim3(D_MODEL / TBN, NTOK / TBM), 256, GEMM_SMEM>>>(att, wbuf + 3 * WN, bo, x, out);
}